// round 10
// baseline (speedup 1.0000x reference)
#include <cuda_runtime.h>
#include <cuda_bf16.h>
#include <math.h>
#include <stdint.h>
#include <mma.h>

using namespace nvcuda;

#define N_NODES 20000
#define N_EDGES 640000
#define HID 256
#define NH (N_NODES * HID)
#define N_LAYERS 5
#define KTOT 512       // stored split K (hi | lo)
#define GKCH 32        // GEMM K elements per pipelined chunk
#define GNCH 24        // 3 segments x 8 chunks: (hi,hi) (lo,hi) (hi,lo)
#define GLDA 40        // gemm smem leading dim (bf16; 80B, 16B-multiple)
#define LDS_STAGE 68   // epilogue staging ld (floats; 272B, 16B-multiple)

// ---------------- scratch ----------------
__device__ float g_h[2][NH];
__device__ float g_q[NH], g_k[NH], g_v[NH], g_sk[NH];
__device__ __align__(256) __nv_bfloat16 g_hb[N_NODES * KTOT];            // A split [M, hi|lo]
__device__ __align__(256) __nv_bfloat16 g_Wb[4 * N_LAYERS * 256 * KTOT]; // B split [N, hi|lo]
__device__ float g_M[46 * HID];
__device__ float g_bias[HID];
__device__ float g_skbias[N_LAYERS * HID];
__device__ int g_deg[N_NODES];
__device__ int g_offs[N_NODES + 1];
__device__ int g_cursor[N_NODES];
__device__ int g_ssrc[N_EDGES];
__device__ int g_seid[N_EDGES];

__device__ __forceinline__ void split_store(float v, __nv_bfloat16* hi_p, __nv_bfloat16* lo_p) {
    __nv_bfloat16 h = __float2bfloat16(v);
    *hi_p = h;
    *lo_p = __float2bfloat16(v - __bfloat162float(h));
}
__device__ __forceinline__ float dot4(float4 a, float4 b) {
    return a.x * b.x + a.y * b.y + a.z * b.z + a.w * b.w;
}
__device__ __forceinline__ void split4(float4 v, uint2* hi, uint2* lo) {
    __nv_bfloat16 hx = __float2bfloat16(v.x), hy = __float2bfloat16(v.y);
    __nv_bfloat16 hz = __float2bfloat16(v.z), hw = __float2bfloat16(v.w);
    __nv_bfloat162 h01 = __nv_bfloat162(hx, hy), h23 = __nv_bfloat162(hz, hw);
    hi->x = *reinterpret_cast<uint32_t*>(&h01);
    hi->y = *reinterpret_cast<uint32_t*>(&h23);
    __nv_bfloat162 l01 = __nv_bfloat162(__float2bfloat16(v.x - __bfloat162float(hx)),
                                        __float2bfloat16(v.y - __bfloat162float(hy)));
    __nv_bfloat162 l23 = __nv_bfloat162(__float2bfloat16(v.z - __bfloat162float(hz)),
                                        __float2bfloat16(v.w - __bfloat162float(hw)));
    lo->x = *reinterpret_cast<uint32_t*>(&l01);
    lo->y = *reinterpret_cast<uint32_t*>(&l23);
}
__device__ __forceinline__ void cp16(void* dst_smem, const void* src) {
    uint32_t d = (uint32_t)__cvta_generic_to_shared(dst_smem);
    asm volatile("cp.async.cg.shared.global [%0], [%1], 16;" :: "r"(d), "l"(src));
}
#define CP_COMMIT() asm volatile("cp.async.commit_group;" ::: "memory")
#define CP_WAIT1() asm volatile("cp.async.wait_group 1;" ::: "memory")
#define CP_WAIT0() asm volatile("cp.async.wait_group 0;" ::: "memory")

// ---------------- weight conversion: W[K,N] fp32 -> Wb[N, 512] bf16 (hi|lo) ----------------
__global__ void wconv_kernel(const float* __restrict__ Wq, const float* __restrict__ Wk,
                             const float* __restrict__ Wv, const float* __restrict__ Wsk) {
    __shared__ float s[32][33];
    int z = blockIdx.z;
    int w = z / N_LAYERS, l = z % N_LAYERS;
    const float* src = (w == 0) ? Wq : (w == 1) ? Wk : (w == 2) ? Wv : Wsk;
    src += l * 65536;
    __nv_bfloat16* dst = g_Wb + (size_t)z * 256 * KTOT;
    int k0 = blockIdx.x * 32, n0 = blockIdx.y * 32;
    int tx = threadIdx.x & 31, ty = threadIdx.x >> 5;
#pragma unroll
    for (int it = 0; it < 4; it++) {
        int r = ty + it * 8;
        s[r][tx] = src[(k0 + r) * 256 + n0 + tx];
    }
    __syncthreads();
#pragma unroll
    for (int it = 0; it < 4; it++) {
        int r = ty + it * 8;
        float v = s[tx][r];
        split_store(v, dst + (size_t)(n0 + r) * KTOT + k0 + tx,
                    dst + (size_t)(n0 + r) * KTOT + 256 + k0 + tx);
    }
}

// ---------------- fused encoder weights + skip-bias fold ----------------
__global__ void fuse_kernel(const float* __restrict__ W_emb, const float* __restrict__ W_t,
                            const float* __restrict__ W_s, const float* __restrict__ W_f,
                            const float* __restrict__ b_emb, const float* __restrict__ b_t,
                            const float* __restrict__ b_s, const float* __restrict__ b_f,
                            const float* __restrict__ bskip, const float* __restrict__ be) {
    int c = threadIdx.x;
    int r = blockIdx.x;
    if (r < 36) {
        float a = 0.f;
        for (int k = 0; k < 256; k++) a += W_emb[r * 256 + k] * W_f[k * 256 + c];
        g_M[r * 256 + c] = a;
    } else if (r < 40) {
        int rr = r - 36;
        float a = 0.f;
        for (int k = 0; k < 256; k++) a += W_t[rr * 256 + k] * W_f[(256 + k) * 256 + c];
        g_M[r * 256 + c] = a;
    } else if (r < 46) {
        int rr = r - 40;
        float a = 0.f;
        for (int k = 0; k < 256; k++) a += W_s[rr * 256 + k] * W_f[(512 + k) * 256 + c];
        g_M[r * 256 + c] = a;
    } else if (r == 46) {
        float a = b_f[c];
        for (int k = 0; k < 256; k++) {
            a += b_emb[k] * W_f[k * 256 + c];
            a += b_t[k] * W_f[(256 + k) * 256 + c];
            a += b_s[k] * W_f[(512 + k) * 256 + c];
        }
        g_bias[c] = a;
    } else {
        int l = r - 47;
        g_skbias[l * 256 + c] = bskip[l * 256 + c] + be[l * 256 + c];
    }
}

// ---------------- encoder ----------------
__global__ void encoder_kernel(const float* __restrict__ x, const float* __restrict__ t,
                               const float* __restrict__ s, const float* __restrict__ ln_g,
                               const float* __restrict__ ln_b) {
    __shared__ float sM[46 * 256];
    __shared__ float sb[256];
    __shared__ float sin_v[46];
    __shared__ float red[16];
    int tid = threadIdx.x;
    for (int i = tid; i < 46 * 256; i += 256) sM[i] = g_M[i];
    sb[tid] = g_bias[tid];
    float lg = ln_g[tid], lb = ln_b[tid];
    __syncthreads();
    for (int node = blockIdx.x; node < N_NODES; node += gridDim.x) {
        if (tid < 36) sin_v[tid] = x[node * 36 + tid];
        else if (tid < 40) sin_v[tid] = t[node * 4 + (tid - 36)];
        else if (tid < 46) sin_v[tid] = s[node * 6 + (tid - 40)];
        __syncthreads();
        float acc = sb[tid];
#pragma unroll
        for (int r = 0; r < 46; r++) acc += sin_v[r] * sM[r * 256 + tid];
        float ssum = acc, ssq = acc * acc;
#pragma unroll
        for (int o = 16; o; o >>= 1) {
            ssum += __shfl_xor_sync(0xffffffffu, ssum, o);
            ssq += __shfl_xor_sync(0xffffffffu, ssq, o);
        }
        if ((tid & 31) == 0) { red[tid >> 5] = ssum; red[8 + (tid >> 5)] = ssq; }
        __syncthreads();
        if (tid < 32) {
            float a = (tid < 8) ? red[tid] : 0.f;
            float b = (tid < 8) ? red[8 + tid] : 0.f;
#pragma unroll
            for (int o = 4; o; o >>= 1) {
                a += __shfl_xor_sync(0xffffffffu, a, o);
                b += __shfl_xor_sync(0xffffffffu, b, o);
            }
            if (tid == 0) { red[0] = a; red[1] = b; }
        }
        __syncthreads();
        float mu = red[0] * (1.f / 256.f);
        float var = red[1] * (1.f / 256.f) - mu * mu;
        float val = fmaxf((acc - mu) * rsqrtf(var + 1e-5f) * lg + lb, 0.f);
        g_h[0][node * 256 + tid] = val;
        split_store(val, g_hb + (size_t)node * KTOT + tid, g_hb + (size_t)node * KTOT + 256 + tid);
        __syncthreads();
    }
}

// ---------------- CSR build ----------------
__global__ void zero_deg_kernel() {
    int i = blockIdx.x * blockDim.x + threadIdx.x;
    if (i < N_NODES) g_deg[i] = 0;
}
__global__ void hist_kernel(const int* __restrict__ ei) {
    int e = blockIdx.x * blockDim.x + threadIdx.x;
    if (e < N_EDGES) atomicAdd(&g_deg[ei[N_EDGES + e]], 1);
}
__global__ void scan_kernel() {
    __shared__ int sh[1024];
    __shared__ int carry;
    int tid = threadIdx.x;
    if (tid == 0) carry = 0;
    __syncthreads();
    for (int base = 0; base < N_NODES; base += 1024) {
        int i = base + tid;
        int v = (i < N_NODES) ? g_deg[i] : 0;
        sh[tid] = v;
        __syncthreads();
        for (int off = 1; off < 1024; off <<= 1) {
            int tadd = (tid >= off) ? sh[tid - off] : 0;
            __syncthreads();
            sh[tid] += tadd;
            __syncthreads();
        }
        int incl = sh[tid];
        if (i < N_NODES) g_offs[i] = carry + incl - v;
        __syncthreads();
        if (tid == 1023) carry += sh[1023];
        __syncthreads();
    }
    if (tid == 0) g_offs[N_NODES] = carry;
}
__global__ void cursor_kernel() {
    int i = blockIdx.x * blockDim.x + threadIdx.x;
    if (i < N_NODES) g_cursor[i] = g_offs[i];
}
__global__ void scatter_kernel(const int* __restrict__ ei) {
    int e = blockIdx.x * blockDim.x + threadIdx.x;
    if (e < N_EDGES) {
        int d = ei[N_EDGES + e];
        int pos = atomicAdd(&g_cursor[d], 1);
        g_ssrc[pos] = ei[e];
        g_seid[pos] = e;
    }
}

// ---------------- bf16 wmma GEMM, 128x128 tile, cp.async double-buffered ----------------
__global__ void __launch_bounds__(256)
gemm_wb(int layer, const float* __restrict__ bq_, const float* __restrict__ bk_,
        const float* __restrict__ bv_) {
    __shared__ __align__(16) __nv_bfloat16 smem_all[2 * 2 * 128 * GLDA];
    __shared__ float sbias[128];

    int tid = threadIdx.x;
    int wid = tid >> 5, lane = tid & 31;
    int wr = wid >> 1, wc = wid & 1;
    int w = blockIdx.z;
    int row0 = blockIdx.x * 128;
    int colblk = blockIdx.y * 128;
    int col0 = colblk + wc * 64;

    const __nv_bfloat16* Bsrc = g_Wb + ((size_t)w * N_LAYERS + layer) * 256 * KTOT;
    float* C;
    const float* bias;
    if (w == 0) { C = g_q; bias = bq_ + layer * 256; }
    else if (w == 1) { C = g_k; bias = bk_ + layer * 256; }
    else if (w == 2) { C = g_v; bias = bv_ + layer * 256; }
    else { C = g_sk; bias = g_skbias + layer * 256; }

    if (tid < 128) sbias[tid] = bias[colblk + tid];

    int l0 = tid, l1 = tid + 256;
    int ar0 = l0 >> 2, ak0 = (l0 & 3) * 8;
    int ar1 = l1 >> 2, ak1 = (l1 & 3) * 8;
    int gr0 = row0 + ar0; if (gr0 >= N_NODES) gr0 = N_NODES - 1;
    int gr1 = row0 + ar1; if (gr1 >= N_NODES) gr1 = N_NODES - 1;

    wmma::fragment<wmma::accumulator, 16, 16, 16, float> acc[2][4];
#pragma unroll
    for (int m = 0; m < 2; m++)
#pragma unroll
        for (int n = 0; n < 4; n++) wmma::fill_fragment(acc[m][n], 0.f);

    auto issue = [&](int c, int buf) {
        int seg = c >> 3, cc = c & 7;
        int aoff = (seg == 1) ? 256 : 0;
        int boff = (seg == 2) ? 256 : 0;
        __nv_bfloat16* As = smem_all + buf * 2 * 128 * GLDA;
        __nv_bfloat16* Bs = As + 128 * GLDA;
        cp16(As + ar0 * GLDA + ak0, g_hb + (size_t)gr0 * KTOT + aoff + cc * GKCH + ak0);
        cp16(As + ar1 * GLDA + ak1, g_hb + (size_t)gr1 * KTOT + aoff + cc * GKCH + ak1);
        cp16(Bs + ar0 * GLDA + ak0, Bsrc + (size_t)(colblk + ar0) * KTOT + boff + cc * GKCH + ak0);
        cp16(Bs + ar1 * GLDA + ak1, Bsrc + (size_t)(colblk + ar1) * KTOT + boff + cc * GKCH + ak1);
        CP_COMMIT();
    };

    issue(0, 0);
    for (int c = 0; c < GNCH; c++) {
        if (c + 1 < GNCH) { issue(c + 1, (c + 1) & 1); CP_WAIT1(); }
        else { CP_WAIT0(); }
        __syncthreads();
        __nv_bfloat16* As = smem_all + (c & 1) * 2 * 128 * GLDA;
        __nv_bfloat16* Bs = As + 128 * GLDA;
#pragma unroll
        for (int ks = 0; ks < 2; ks++) {
            wmma::fragment<wmma::matrix_a, 16, 16, 16, __nv_bfloat16, wmma::row_major> af[2];
            wmma::fragment<wmma::matrix_b, 16, 16, 16, __nv_bfloat16, wmma::col_major> bf[4];
#pragma unroll
            for (int m = 0; m < 2; m++)
                wmma::load_matrix_sync(af[m], As + (wr * 32 + m * 16) * GLDA + ks * 16, GLDA);
#pragma unroll
            for (int n = 0; n < 4; n++)
                wmma::load_matrix_sync(bf[n], Bs + (wc * 64 + n * 16) * GLDA + ks * 16, GLDA);
#pragma unroll
            for (int m = 0; m < 2; m++)
#pragma unroll
                for (int n = 0; n < 4; n++) wmma::mma_sync(acc[m][n], af[m], bf[n], acc[m][n]);
        }
        __syncthreads();
    }

    float* stage = reinterpret_cast<float*>(smem_all) + wid * 16 * LDS_STAGE;
#pragma unroll
    for (int m = 0; m < 2; m++) {
        __syncwarp();
#pragma unroll
        for (int n = 0; n < 4; n++)
            wmma::store_matrix_sync(stage + n * 16, acc[m][n], LDS_STAGE, wmma::mem_row_major);
        __syncwarp();
        int rbase = row0 + wr * 32 + m * 16;
#pragma unroll
        for (int i = lane; i < 16 * 64; i += 32) {
            int r = i >> 6, cc2 = i & 63;
            int gr = rbase + r;
            if (gr < N_NODES)
                C[(size_t)gr * 256 + col0 + cc2] = stage[r * LDS_STAGE + cc2] + sbias[wc * 64 + cc2];
        }
        __syncwarp();
    }
}

// ---------------- attention: float4 lanes, 2-edge unrolled online softmax ----------------
__global__ void attn_kernel(const float* __restrict__ We_l, const float* __restrict__ edge_attr,
                            int pin) {
    __shared__ float sWe[8 * 256];
    for (int i = threadIdx.x; i < 2048; i += blockDim.x) sWe[i] = We_l[i];
    __syncthreads();
    const float4* sWe4 = reinterpret_cast<const float4*>(sWe);
    int w = (blockIdx.x * blockDim.x + threadIdx.x) >> 5;
    int lane = threadIdx.x & 31;
    if (w >= N_NODES) return;
    float* hout = g_h[pin ^ 1];

    float4 q0 = *reinterpret_cast<const float4*>(g_q + (size_t)w * 256 + lane * 4);
    float4 q1 = *reinterpret_cast<const float4*>(g_q + (size_t)w * 256 + 128 + lane * 4);

    float qwe[8];
#pragma unroll
    for (int d = 0; d < 8; d++) {
        float p = dot4(q0, sWe4[d * 64 + lane]) + dot4(q1, sWe4[d * 64 + 32 + lane]);
#pragma unroll
        for (int o = 16; o; o >>= 1) p += __shfl_xor_sync(0xffffffffu, p, o);
        qwe[d] = p;
    }

    float m = -INFINITY, den = 0.f;
    float4 acc0 = make_float4(0, 0, 0, 0), acc1 = make_float4(0, 0, 0, 0);
    float4 pea0 = make_float4(0, 0, 0, 0), pea1 = make_float4(0, 0, 0, 0);
    int beg = g_offs[w], end = g_offs[w + 1];

    int t = beg;
    for (; t + 2 <= end; t += 2) {
        int srcA = g_ssrc[t], eidA = g_seid[t];
        int srcB = g_ssrc[t + 1], eidB = g_seid[t + 1];
        const float4* krA = reinterpret_cast<const float4*>(g_k + (size_t)srcA * 256);
        const float4* vrA = reinterpret_cast<const float4*>(g_v + (size_t)srcA * 256);
        const float4* arA = reinterpret_cast<const float4*>(edge_attr + (size_t)eidA * 8);
        const float4* krB = reinterpret_cast<const float4*>(g_k + (size_t)srcB * 256);
        const float4* vrB = reinterpret_cast<const float4*>(g_v + (size_t)srcB * 256);
        const float4* arB = reinterpret_cast<const float4*>(edge_attr + (size_t)eidB * 8);
        float4 kA0 = krA[lane], kA1 = krA[32 + lane];
        float4 kB0 = krB[lane], kB1 = krB[32 + lane];
        float4 vA0 = vrA[lane], vA1 = vrA[32 + lane];
        float4 vB0 = vrB[lane], vB1 = vrB[32 + lane];
        float4 eA0 = arA[0], eA1 = arA[1];
        float4 eB0 = arB[0], eB1 = arB[1];

        float dA = dot4(q0, kA0) + dot4(q1, kA1);
        float dB = dot4(q0, kB0) + dot4(q1, kB1);
#pragma unroll
        for (int o = 16; o; o >>= 1) {
            dA += __shfl_xor_sync(0xffffffffu, dA, o);
            dB += __shfl_xor_sync(0xffffffffu, dB, o);
        }
        float aA = (dA + qwe[0] * eA0.x + qwe[1] * eA0.y + qwe[2] * eA0.z + qwe[3] * eA0.w +
                    qwe[4] * eA1.x + qwe[5] * eA1.y + qwe[6] * eA1.z + qwe[7] * eA1.w) * 0.0625f;
        float aB = (dB + qwe[0] * eB0.x + qwe[1] * eB0.y + qwe[2] * eB0.z + qwe[3] * eB0.w +
                    qwe[4] * eB1.x + qwe[5] * eB1.y + qwe[6] * eB1.z + qwe[7] * eB1.w) * 0.0625f;
        float mn = fmaxf(m, fmaxf(aA, aB));
        float corr = __expf(m - mn);
        float pA = __expf(aA - mn);
        float pB = __expf(aB - mn);
        m = mn;
        den = den * corr + pA + pB;
        acc0.x = acc0.x * corr + pA * vA0.x + pB * vB0.x;
        acc0.y = acc0.y * corr + pA * vA0.y + pB * vB0.y;
        acc0.z = acc0.z * corr + pA * vA0.z + pB * vB0.z;
        acc0.w = acc0.w * corr + pA * vA0.w + pB * vB0.w;
        acc1.x = acc1.x * corr + pA * vA1.x + pB * vB1.x;
        acc1.y = acc1.y * corr + pA * vA1.y + pB * vB1.y;
        acc1.z = acc1.z * corr + pA * vA1.z + pB * vB1.z;
        acc1.w = acc1.w * corr + pA * vA1.w + pB * vB1.w;
        pea0.x = pea0.x * corr + pA * eA0.x + pB * eB0.x;
        pea0.y = pea0.y * corr + pA * eA0.y + pB * eB0.y;
        pea0.z = pea0.z * corr + pA * eA0.z + pB * eB0.z;
        pea0.w = pea0.w * corr + pA * eA0.w + pB * eB0.w;
        pea1.x = pea1.x * corr + pA * eA1.x + pB * eB1.x;
        pea1.y = pea1.y * corr + pA * eA1.y + pB * eB1.y;
        pea1.z = pea1.z * corr + pA * eA1.z + pB * eB1.z;
        pea1.w = pea1.w * corr + pA * eA1.w + pB * eB1.w;
    }
    if (t < end) {  // tail edge
        int src = g_ssrc[t], eid = g_seid[t];
        const float4* kr = reinterpret_cast<const float4*>(g_k + (size_t)src * 256);
        const float4* vr = reinterpret_cast<const float4*>(g_v + (size_t)src * 256);
        const float4* ar = reinterpret_cast<const float4*>(edge_attr + (size_t)eid * 8);
        float4 k0 = kr[lane], k1 = kr[32 + lane];
        float4 v0 = vr[lane], v1 = vr[32 + lane];
        float4 e0 = ar[0], e1 = ar[1];
        float dot = dot4(q0, k0) + dot4(q1, k1);
#pragma unroll
        for (int o = 16; o; o >>= 1) dot += __shfl_xor_sync(0xffffffffu, dot, o);
        float alpha = (dot + qwe[0] * e0.x + qwe[1] * e0.y + qwe[2] * e0.z + qwe[3] * e0.w +
                       qwe[4] * e1.x + qwe[5] * e1.y + qwe[6] * e1.z + qwe[7] * e1.w) * 0.0625f;
        float mn = fmaxf(m, alpha);
        float corr = __expf(m - mn);
        float p = __expf(alpha - mn);
        m = mn;
        den = den * corr + p;
        acc0.x = acc0.x * corr + p * v0.x; acc0.y = acc0.y * corr + p * v0.y;
        acc0.z = acc0.z * corr + p * v0.z; acc0.w = acc0.w * corr + p * v0.w;
        acc1.x = acc1.x * corr + p * v1.x; acc1.y = acc1.y * corr + p * v1.y;
        acc1.z = acc1.z * corr + p * v1.z; acc1.w = acc1.w * corr + p * v1.w;
        pea0.x = pea0.x * corr + p * e0.x; pea0.y = pea0.y * corr + p * e0.y;
        pea0.z = pea0.z * corr + p * e0.z; pea0.w = pea0.w * corr + p * e0.w;
        pea1.x = pea1.x * corr + p * e1.x; pea1.y = pea1.y * corr + p * e1.y;
        pea1.z = pea1.z * corr + p * e1.z; pea1.w = pea1.w * corr + p * e1.w;
    }

    float inv = 1.f / (den + 1e-16f);
    float pe[8] = {pea0.x, pea0.y, pea0.z, pea0.w, pea1.x, pea1.y, pea1.z, pea1.w};
    float4 ex0 = make_float4(0, 0, 0, 0), ex1 = make_float4(0, 0, 0, 0);
#pragma unroll
    for (int d = 0; d < 8; d++) {
        float4 w0 = sWe4[d * 64 + lane], w1 = sWe4[d * 64 + 32 + lane];
        ex0.x += pe[d] * w0.x; ex0.y += pe[d] * w0.y; ex0.z += pe[d] * w0.z; ex0.w += pe[d] * w0.w;
        ex1.x += pe[d] * w1.x; ex1.y += pe[d] * w1.y; ex1.z += pe[d] * w1.z; ex1.w += pe[d] * w1.w;
    }
    float4 sk0 = *reinterpret_cast<const float4*>(g_sk + (size_t)w * 256 + lane * 4);
    float4 sk1 = *reinterpret_cast<const float4*>(g_sk + (size_t)w * 256 + 128 + lane * 4);
    float4 o0, o1;
    o0.x = fmaxf((acc0.x + ex0.x) * inv + sk0.x, 0.f);
    o0.y = fmaxf((acc0.y + ex0.y) * inv + sk0.y, 0.f);
    o0.z = fmaxf((acc0.z + ex0.z) * inv + sk0.z, 0.f);
    o0.w = fmaxf((acc0.w + ex0.w) * inv + sk0.w, 0.f);
    o1.x = fmaxf((acc1.x + ex1.x) * inv + sk1.x, 0.f);
    o1.y = fmaxf((acc1.y + ex1.y) * inv + sk1.y, 0.f);
    o1.z = fmaxf((acc1.z + ex1.z) * inv + sk1.z, 0.f);
    o1.w = fmaxf((acc1.w + ex1.w) * inv + sk1.w, 0.f);
    *reinterpret_cast<float4*>(hout + (size_t)w * 256 + lane * 4) = o0;
    *reinterpret_cast<float4*>(hout + (size_t)w * 256 + 128 + lane * 4) = o1;
    uint2 hi, lo;
    split4(o0, &hi, &lo);
    *reinterpret_cast<uint2*>(g_hb + (size_t)w * KTOT + lane * 4) = hi;
    *reinterpret_cast<uint2*>(g_hb + (size_t)w * KTOT + 256 + lane * 4) = lo;
    split4(o1, &hi, &lo);
    *reinterpret_cast<uint2*>(g_hb + (size_t)w * KTOT + 128 + lane * 4) = hi;
    *reinterpret_cast<uint2*>(g_hb + (size_t)w * KTOT + 256 + 128 + lane * 4) = lo;
}

// ---------------- decoder ----------------
__global__ void dec_kernel(const float* __restrict__ Wd, const float* __restrict__ bd,
                           float* __restrict__ out) {
    __shared__ float sW[18 * 256];
    __shared__ float sb[18];
    for (int i = threadIdx.x; i < 18 * 256; i += blockDim.x) {
        int j = i / 18, o = i % 18;
        sW[o * 256 + j] = Wd[i];
    }
    if (threadIdx.x < 18) sb[threadIdx.x] = bd[threadIdx.x];
    __syncthreads();
    int w = (blockIdx.x * blockDim.x + threadIdx.x) >> 5;
    int lane = threadIdx.x & 31;
    if (w >= N_NODES) return;
    const float* h = g_h[1];
    float hr[8];
#pragma unroll
    for (int i = 0; i < 8; i++) hr[i] = h[(size_t)w * 256 + lane + 32 * i];
    for (int o = 0; o < 18; o++) {
        float p = 0.f;
#pragma unroll
        for (int i = 0; i < 8; i++) p += hr[i] * sW[o * 256 + lane + 32 * i];
#pragma unroll
        for (int off = 16; off; off >>= 1) p += __shfl_xor_sync(0xffffffffu, p, off);
        if (lane == 0) out[w * 18 + o] = p + sb[o];
    }
}

// ---------------- launch ----------------
extern "C" void kernel_launch(void* const* d_in, const int* in_sizes, int n_in,
                              void* d_out, int out_size) {
    const float* x = (const float*)d_in[0];
    const int* ei = (const int*)d_in[1];
    const float* edge_attr = (const float*)d_in[2];
    const float* t = (const float*)d_in[3];
    const float* s = (const float*)d_in[4];
    const float* W_emb = (const float*)d_in[5];
    const float* b_emb = (const float*)d_in[6];
    const float* W_t = (const float*)d_in[7];
    const float* b_t = (const float*)d_in[8];
    const float* W_s = (const float*)d_in[9];
    const float* b_s = (const float*)d_in[10];
    const float* W_f = (const float*)d_in[11];
    const float* b_f = (const float*)d_in[12];
    const float* ln_g = (const float*)d_in[13];
    const float* ln_b = (const float*)d_in[14];
    const float* Wq = (const float*)d_in[15];
    const float* bq = (const float*)d_in[16];
    const float* Wk = (const float*)d_in[17];
    const float* bk = (const float*)d_in[18];
    const float* Wv = (const float*)d_in[19];
    const float* bv = (const float*)d_in[20];
    const float* We = (const float*)d_in[21];
    const float* be = (const float*)d_in[22];
    const float* Wskip = (const float*)d_in[23];
    const float* bskip = (const float*)d_in[24];
    const float* W_dec = (const float*)d_in[25];
    const float* b_dec = (const float*)d_in[26];
    float* out = (float*)d_out;
    (void)in_sizes; (void)n_in; (void)out_size;

    wconv_kernel<<<dim3(8, 8, 20), 256>>>(Wq, Wk, Wv, Wskip);                        // 0
    fuse_kernel<<<52, 256>>>(W_emb, W_t, W_s, W_f, b_emb, b_t, b_s, b_f, bskip, be); // 1
    encoder_kernel<<<296, 256>>>(x, t, s, ln_g, ln_b);                               // 2

    dim3 ggrid(157, 2, 4);
    gemm_wb<<<ggrid, 256>>>(0, bq, bk, bv);                                          // 3 <- profiled

    zero_deg_kernel<<<(N_NODES + 255) / 256, 256>>>();  // 4
    hist_kernel<<<(N_EDGES + 255) / 256, 256>>>(ei);    // 5
    scan_kernel<<<1, 1024>>>();                         // 6
    cursor_kernel<<<(N_NODES + 255) / 256, 256>>>();    // 7
    scatter_kernel<<<(N_EDGES + 255) / 256, 256>>>(ei); // 8

    int attn_blocks = (N_NODES * 32 + 255) / 256;
    attn_kernel<<<attn_blocks, 256>>>(We + 0 * 2048, edge_attr, 0);                  // 9
    for (int L = 1; L < N_LAYERS; L++) {
        int pin = L & 1;
        gemm_wb<<<ggrid, 256>>>(L, bq, bk, bv);
        attn_kernel<<<attn_blocks, 256>>>(We + L * 2048, edge_attr, pin);
    }
    dec_kernel<<<attn_blocks, 256>>>(W_dec, b_dec, out);
}

// round 11
// speedup vs baseline: 1.2128x; 1.2128x over previous
#include <cuda_runtime.h>
#include <cuda_bf16.h>
#include <math.h>
#include <stdint.h>
#include <mma.h>

using namespace nvcuda;

#define N_NODES 20000
#define N_EDGES 640000
#define HID 256
#define NH (N_NODES * HID)
#define N_LAYERS 5
#define KTOT 512       // stored split K (hi | lo)
#define GKCH 32        // GEMM K elements per pipelined chunk
#define GNCH 24        // 3 segments x 8 chunks: (hi,hi) (lo,hi) (hi,lo)
#define GLDA 40        // gemm smem leading dim (bf16; 80B, 16B-multiple)
#define LDS_STAGE 68   // epilogue staging ld (floats; 272B, 16B-multiple)
#define NBLK 79        // ceil(20000/256)

// ---------------- scratch ----------------
__device__ float g_h[2][NH];
__device__ float g_q[NH], g_k[NH], g_v[NH], g_sk[NH];
__device__ __align__(256) __nv_bfloat16 g_hb[N_NODES * KTOT];            // A split [M, hi|lo]
__device__ __align__(256) __nv_bfloat16 g_Wb[4 * N_LAYERS * 256 * KTOT]; // B split [N, hi|lo]
__device__ float g_M[46 * HID];
__device__ float g_bias[HID];
__device__ float g_skbias[N_LAYERS * HID];
__device__ int g_deg[N_NODES];
__device__ int g_offs[N_NODES + 1];
__device__ int g_bsum[NBLK];
__device__ int g_cursor[N_NODES];
__device__ int g_ssrc[N_EDGES];
__device__ int g_seid[N_EDGES];

__device__ __forceinline__ void split_store(float v, __nv_bfloat16* hi_p, __nv_bfloat16* lo_p) {
    __nv_bfloat16 h = __float2bfloat16(v);
    *hi_p = h;
    *lo_p = __float2bfloat16(v - __bfloat162float(h));
}
__device__ __forceinline__ float dot4(float4 a, float4 b) {
    return a.x * b.x + a.y * b.y + a.z * b.z + a.w * b.w;
}
__device__ __forceinline__ void split4(float4 v, uint2* hi, uint2* lo) {
    __nv_bfloat16 hx = __float2bfloat16(v.x), hy = __float2bfloat16(v.y);
    __nv_bfloat16 hz = __float2bfloat16(v.z), hw = __float2bfloat16(v.w);
    __nv_bfloat162 h01 = __nv_bfloat162(hx, hy), h23 = __nv_bfloat162(hz, hw);
    hi->x = *reinterpret_cast<uint32_t*>(&h01);
    hi->y = *reinterpret_cast<uint32_t*>(&h23);
    __nv_bfloat162 l01 = __nv_bfloat162(__float2bfloat16(v.x - __bfloat162float(hx)),
                                        __float2bfloat16(v.y - __bfloat162float(hy)));
    __nv_bfloat162 l23 = __nv_bfloat162(__float2bfloat16(v.z - __bfloat162float(hz)),
                                        __float2bfloat16(v.w - __bfloat162float(hw)));
    lo->x = *reinterpret_cast<uint32_t*>(&l01);
    lo->y = *reinterpret_cast<uint32_t*>(&l23);
}
__device__ __forceinline__ void cp16(void* dst_smem, const void* src) {
    uint32_t d = (uint32_t)__cvta_generic_to_shared(dst_smem);
    asm volatile("cp.async.cg.shared.global [%0], [%1], 16;" :: "r"(d), "l"(src));
}
#define CP_COMMIT() asm volatile("cp.async.commit_group;" ::: "memory")
#define CP_WAIT1() asm volatile("cp.async.wait_group 1;" ::: "memory")
#define CP_WAIT0() asm volatile("cp.async.wait_group 0;" ::: "memory")

// ---------------- weight conversion: W[K,N] fp32 -> Wb[N, 512] bf16 (hi|lo) ----------------
__global__ void wconv_kernel(const float* __restrict__ Wq, const float* __restrict__ Wk,
                             const float* __restrict__ Wv, const float* __restrict__ Wsk) {
    __shared__ float s[32][33];
    int z = blockIdx.z;
    int w = z / N_LAYERS, l = z % N_LAYERS;
    const float* src = (w == 0) ? Wq : (w == 1) ? Wk : (w == 2) ? Wv : Wsk;
    src += l * 65536;
    __nv_bfloat16* dst = g_Wb + (size_t)z * 256 * KTOT;
    int k0 = blockIdx.x * 32, n0 = blockIdx.y * 32;
    int tx = threadIdx.x & 31, ty = threadIdx.x >> 5;
#pragma unroll
    for (int it = 0; it < 4; it++) {
        int r = ty + it * 8;
        s[r][tx] = src[(k0 + r) * 256 + n0 + tx];
    }
    __syncthreads();
#pragma unroll
    for (int it = 0; it < 4; it++) {
        int r = ty + it * 8;
        float v = s[tx][r];
        split_store(v, dst + (size_t)(n0 + r) * KTOT + k0 + tx,
                    dst + (size_t)(n0 + r) * KTOT + 256 + k0 + tx);
    }
}

// ---------------- fused encoder weights + skip-bias fold ----------------
__global__ void fuse_kernel(const float* __restrict__ W_emb, const float* __restrict__ W_t,
                            const float* __restrict__ W_s, const float* __restrict__ W_f,
                            const float* __restrict__ b_emb, const float* __restrict__ b_t,
                            const float* __restrict__ b_s, const float* __restrict__ b_f,
                            const float* __restrict__ bskip, const float* __restrict__ be) {
    int c = threadIdx.x;
    int r = blockIdx.x;
    if (r < 36) {
        float a = 0.f;
        for (int k = 0; k < 256; k++) a += W_emb[r * 256 + k] * W_f[k * 256 + c];
        g_M[r * 256 + c] = a;
    } else if (r < 40) {
        int rr = r - 36;
        float a = 0.f;
        for (int k = 0; k < 256; k++) a += W_t[rr * 256 + k] * W_f[(256 + k) * 256 + c];
        g_M[r * 256 + c] = a;
    } else if (r < 46) {
        int rr = r - 40;
        float a = 0.f;
        for (int k = 0; k < 256; k++) a += W_s[rr * 256 + k] * W_f[(512 + k) * 256 + c];
        g_M[r * 256 + c] = a;
    } else if (r == 46) {
        float a = b_f[c];
        for (int k = 0; k < 256; k++) {
            a += b_emb[k] * W_f[k * 256 + c];
            a += b_t[k] * W_f[(256 + k) * 256 + c];
            a += b_s[k] * W_f[(512 + k) * 256 + c];
        }
        g_bias[c] = a;
    } else {
        int l = r - 47;
        g_skbias[l * 256 + c] = bskip[l * 256 + c] + be[l * 256 + c];
    }
}

// ---------------- encoder ----------------
__global__ void encoder_kernel(const float* __restrict__ x, const float* __restrict__ t,
                               const float* __restrict__ s, const float* __restrict__ ln_g,
                               const float* __restrict__ ln_b) {
    __shared__ float sM[46 * 256];
    __shared__ float sb[256];
    __shared__ float sin_v[46];
    __shared__ float red[16];
    int tid = threadIdx.x;
    for (int i = tid; i < 46 * 256; i += 256) sM[i] = g_M[i];
    sb[tid] = g_bias[tid];
    float lg = ln_g[tid], lb = ln_b[tid];
    __syncthreads();
    for (int node = blockIdx.x; node < N_NODES; node += gridDim.x) {
        if (tid < 36) sin_v[tid] = x[node * 36 + tid];
        else if (tid < 40) sin_v[tid] = t[node * 4 + (tid - 36)];
        else if (tid < 46) sin_v[tid] = s[node * 6 + (tid - 40)];
        __syncthreads();
        float acc = sb[tid];
#pragma unroll
        for (int r = 0; r < 46; r++) acc += sin_v[r] * sM[r * 256 + tid];
        float ssum = acc, ssq = acc * acc;
#pragma unroll
        for (int o = 16; o; o >>= 1) {
            ssum += __shfl_xor_sync(0xffffffffu, ssum, o);
            ssq += __shfl_xor_sync(0xffffffffu, ssq, o);
        }
        if ((tid & 31) == 0) { red[tid >> 5] = ssum; red[8 + (tid >> 5)] = ssq; }
        __syncthreads();
        if (tid < 32) {
            float a = (tid < 8) ? red[tid] : 0.f;
            float b = (tid < 8) ? red[8 + tid] : 0.f;
#pragma unroll
            for (int o = 4; o; o >>= 1) {
                a += __shfl_xor_sync(0xffffffffu, a, o);
                b += __shfl_xor_sync(0xffffffffu, b, o);
            }
            if (tid == 0) { red[0] = a; red[1] = b; }
        }
        __syncthreads();
        float mu = red[0] * (1.f / 256.f);
        float var = red[1] * (1.f / 256.f) - mu * mu;
        float val = fmaxf((acc - mu) * rsqrtf(var + 1e-5f) * lg + lb, 0.f);
        g_h[0][node * 256 + tid] = val;
        split_store(val, g_hb + (size_t)node * KTOT + tid, g_hb + (size_t)node * KTOT + 256 + tid);
        __syncthreads();
    }
}

// ---------------- CSR build (3-phase scan) ----------------
__global__ void zero_deg_kernel() {
    int i = blockIdx.x * blockDim.x + threadIdx.x;
    if (i < N_NODES) g_deg[i] = 0;
}
__global__ void hist_kernel(const int* __restrict__ ei) {
    int e = blockIdx.x * blockDim.x + threadIdx.x;
    if (e < N_EDGES) atomicAdd(&g_deg[ei[N_EDGES + e]], 1);
}
// per-block exclusive scan of deg -> g_offs (block-local), block totals -> g_bsum
__global__ void scanA_kernel() {
    __shared__ int wsum[8];
    int b = blockIdx.x, tid = threadIdx.x;
    int i = b * 256 + tid;
    int lane = tid & 31, wid = tid >> 5;
    int v = (i < N_NODES) ? g_deg[i] : 0;
    int x = v;
#pragma unroll
    for (int o = 1; o < 32; o <<= 1) {
        int y = __shfl_up_sync(0xffffffffu, x, o);
        if (lane >= o) x += y;
    }
    if (lane == 31) wsum[wid] = x;
    __syncthreads();
    if (wid == 0) {
        int s = (lane < 8) ? wsum[lane] : 0;
#pragma unroll
        for (int o = 1; o < 8; o <<= 1) {
            int y = __shfl_up_sync(0xffffffffu, s, o);
            if (lane >= o) s += y;
        }
        if (lane < 8) wsum[lane] = s;  // inclusive warp sums
    }
    __syncthreads();
    int base = (wid > 0) ? wsum[wid - 1] : 0;
    int incl = base + x;
    if (i < N_NODES) g_offs[i] = incl - v;  // exclusive, block-local
    if (tid == 255) g_bsum[b] = incl;       // block total
}
// tiny serial scan of block totals
__global__ void scanB_kernel() {
    int total = 0;
    for (int b = 0; b < NBLK; b++) {
        int t = g_bsum[b];
        g_bsum[b] = total;
        total += t;
    }
    g_offs[N_NODES] = total;
}
// add block bases; init cursor
__global__ void scanC_kernel() {
    int i = blockIdx.x * 256 + threadIdx.x;
    if (i < N_NODES) {
        int o = g_offs[i] + g_bsum[blockIdx.x];
        g_offs[i] = o;
        g_cursor[i] = o;
    }
}
__global__ void scatter_kernel(const int* __restrict__ ei) {
    int e = blockIdx.x * blockDim.x + threadIdx.x;
    if (e < N_EDGES) {
        int d = ei[N_EDGES + e];
        int pos = atomicAdd(&g_cursor[d], 1);
        g_ssrc[pos] = ei[e];
        g_seid[pos] = e;
    }
}

// ---------------- bf16 wmma GEMM, 128x128 tile, cp.async double-buffered ----------------
__global__ void __launch_bounds__(256)
gemm_wb(int layer, const float* __restrict__ bq_, const float* __restrict__ bk_,
        const float* __restrict__ bv_) {
    __shared__ __align__(16) __nv_bfloat16 smem_all[2 * 2 * 128 * GLDA];
    __shared__ float sbias[128];

    int tid = threadIdx.x;
    int wid = tid >> 5, lane = tid & 31;
    int wr = wid >> 1, wc = wid & 1;
    int w = blockIdx.z;
    int row0 = blockIdx.x * 128;
    int colblk = blockIdx.y * 128;
    int col0 = colblk + wc * 64;

    const __nv_bfloat16* Bsrc = g_Wb + ((size_t)w * N_LAYERS + layer) * 256 * KTOT;
    float* C;
    const float* bias;
    if (w == 0) { C = g_q; bias = bq_ + layer * 256; }
    else if (w == 1) { C = g_k; bias = bk_ + layer * 256; }
    else if (w == 2) { C = g_v; bias = bv_ + layer * 256; }
    else { C = g_sk; bias = g_skbias + layer * 256; }

    if (tid < 128) sbias[tid] = bias[colblk + tid];

    int l0 = tid, l1 = tid + 256;
    int ar0 = l0 >> 2, ak0 = (l0 & 3) * 8;
    int ar1 = l1 >> 2, ak1 = (l1 & 3) * 8;
    int gr0 = row0 + ar0; if (gr0 >= N_NODES) gr0 = N_NODES - 1;
    int gr1 = row0 + ar1; if (gr1 >= N_NODES) gr1 = N_NODES - 1;

    wmma::fragment<wmma::accumulator, 16, 16, 16, float> acc[2][4];
#pragma unroll
    for (int m = 0; m < 2; m++)
#pragma unroll
        for (int n = 0; n < 4; n++) wmma::fill_fragment(acc[m][n], 0.f);

    auto issue = [&](int c, int buf) {
        int seg = c >> 3, cc = c & 7;
        int aoff = (seg == 1) ? 256 : 0;
        int boff = (seg == 2) ? 256 : 0;
        __nv_bfloat16* As = smem_all + buf * 2 * 128 * GLDA;
        __nv_bfloat16* Bs = As + 128 * GLDA;
        cp16(As + ar0 * GLDA + ak0, g_hb + (size_t)gr0 * KTOT + aoff + cc * GKCH + ak0);
        cp16(As + ar1 * GLDA + ak1, g_hb + (size_t)gr1 * KTOT + aoff + cc * GKCH + ak1);
        cp16(Bs + ar0 * GLDA + ak0, Bsrc + (size_t)(colblk + ar0) * KTOT + boff + cc * GKCH + ak0);
        cp16(Bs + ar1 * GLDA + ak1, Bsrc + (size_t)(colblk + ar1) * KTOT + boff + cc * GKCH + ak1);
        CP_COMMIT();
    };

    issue(0, 0);
    for (int c = 0; c < GNCH; c++) {
        if (c + 1 < GNCH) { issue(c + 1, (c + 1) & 1); CP_WAIT1(); }
        else { CP_WAIT0(); }
        __syncthreads();
        __nv_bfloat16* As = smem_all + (c & 1) * 2 * 128 * GLDA;
        __nv_bfloat16* Bs = As + 128 * GLDA;
#pragma unroll
        for (int ks = 0; ks < 2; ks++) {
            wmma::fragment<wmma::matrix_a, 16, 16, 16, __nv_bfloat16, wmma::row_major> af[2];
            wmma::fragment<wmma::matrix_b, 16, 16, 16, __nv_bfloat16, wmma::col_major> bf[4];
#pragma unroll
            for (int m = 0; m < 2; m++)
                wmma::load_matrix_sync(af[m], As + (wr * 32 + m * 16) * GLDA + ks * 16, GLDA);
#pragma unroll
            for (int n = 0; n < 4; n++)
                wmma::load_matrix_sync(bf[n], Bs + (wc * 64 + n * 16) * GLDA + ks * 16, GLDA);
#pragma unroll
            for (int m = 0; m < 2; m++)
#pragma unroll
                for (int n = 0; n < 4; n++) wmma::mma_sync(acc[m][n], af[m], bf[n], acc[m][n]);
        }
        __syncthreads();
    }

    float* stage = reinterpret_cast<float*>(smem_all) + wid * 16 * LDS_STAGE;
#pragma unroll
    for (int m = 0; m < 2; m++) {
        __syncwarp();
#pragma unroll
        for (int n = 0; n < 4; n++)
            wmma::store_matrix_sync(stage + n * 16, acc[m][n], LDS_STAGE, wmma::mem_row_major);
        __syncwarp();
        int rbase = row0 + wr * 32 + m * 16;
#pragma unroll
        for (int i = lane; i < 16 * 64; i += 32) {
            int r = i >> 6, cc2 = i & 63;
            int gr = rbase + r;
            if (gr < N_NODES)
                C[(size_t)gr * 256 + col0 + cc2] = stage[r * LDS_STAGE + cc2] + sbias[wc * 64 + cc2];
        }
        __syncwarp();
    }
}

// ---------------- attention: float4 lanes (R9 loop), occupancy-boosted ----------------
__global__ void __launch_bounds__(256, 3)
attn_kernel(const float* __restrict__ We_l, const float* __restrict__ edge_attr, int pin) {
    __shared__ float sWe[8 * 256];
    for (int i = threadIdx.x; i < 2048; i += blockDim.x) sWe[i] = We_l[i];
    __syncthreads();
    const float4* sWe4 = reinterpret_cast<const float4*>(sWe);
    int w = (blockIdx.x * blockDim.x + threadIdx.x) >> 5;
    int lane = threadIdx.x & 31;
    if (w >= N_NODES) return;
    float* hout = g_h[pin ^ 1];

    float4 q0 = *reinterpret_cast<const float4*>(g_q + (size_t)w * 256 + lane * 4);
    float4 q1 = *reinterpret_cast<const float4*>(g_q + (size_t)w * 256 + 128 + lane * 4);

    float qwe[8];
#pragma unroll
    for (int d = 0; d < 8; d++) {
        float p = dot4(q0, sWe4[d * 64 + lane]) + dot4(q1, sWe4[d * 64 + 32 + lane]);
#pragma unroll
        for (int o = 16; o; o >>= 1) p += __shfl_xor_sync(0xffffffffu, p, o);
        qwe[d] = p;
    }

    float m = -INFINITY, den = 0.f;
    float4 acc0 = make_float4(0, 0, 0, 0), acc1 = make_float4(0, 0, 0, 0);
    float4 pea0 = make_float4(0, 0, 0, 0), pea1 = make_float4(0, 0, 0, 0);
    int beg = g_offs[w], end = g_offs[w + 1];
    for (int t = beg; t < end; t++) {
        int src = g_ssrc[t];
        int eid = g_seid[t];
        const float4* kr = reinterpret_cast<const float4*>(g_k + (size_t)src * 256);
        const float4* vr = reinterpret_cast<const float4*>(g_v + (size_t)src * 256);
        const float4* ar = reinterpret_cast<const float4*>(edge_attr + (size_t)eid * 8);
        float4 k0 = kr[lane], k1 = kr[32 + lane];
        float4 v0 = vr[lane], v1 = vr[32 + lane];
        float4 e0 = ar[0], e1 = ar[1];

        float dot = dot4(q0, k0) + dot4(q1, k1);
#pragma unroll
        for (int o = 16; o; o >>= 1) dot += __shfl_xor_sync(0xffffffffu, dot, o);
        float alpha = dot + qwe[0] * e0.x + qwe[1] * e0.y + qwe[2] * e0.z + qwe[3] * e0.w +
                      qwe[4] * e1.x + qwe[5] * e1.y + qwe[6] * e1.z + qwe[7] * e1.w;
        alpha *= 0.0625f;
        float mn = fmaxf(m, alpha);
        float corr = __expf(m - mn);
        float p = __expf(alpha - mn);
        m = mn;
        den = den * corr + p;
        acc0.x = acc0.x * corr + p * v0.x; acc0.y = acc0.y * corr + p * v0.y;
        acc0.z = acc0.z * corr + p * v0.z; acc0.w = acc0.w * corr + p * v0.w;
        acc1.x = acc1.x * corr + p * v1.x; acc1.y = acc1.y * corr + p * v1.y;
        acc1.z = acc1.z * corr + p * v1.z; acc1.w = acc1.w * corr + p * v1.w;
        pea0.x = pea0.x * corr + p * e0.x; pea0.y = pea0.y * corr + p * e0.y;
        pea0.z = pea0.z * corr + p * e0.z; pea0.w = pea0.w * corr + p * e0.w;
        pea1.x = pea1.x * corr + p * e1.x; pea1.y = pea1.y * corr + p * e1.y;
        pea1.z = pea1.z * corr + p * e1.z; pea1.w = pea1.w * corr + p * e1.w;
    }
    float inv = 1.f / (den + 1e-16f);
    float pe[8] = {pea0.x, pea0.y, pea0.z, pea0.w, pea1.x, pea1.y, pea1.z, pea1.w};
    float4 ex0 = make_float4(0, 0, 0, 0), ex1 = make_float4(0, 0, 0, 0);
#pragma unroll
    for (int d = 0; d < 8; d++) {
        float4 w0 = sWe4[d * 64 + lane], w1 = sWe4[d * 64 + 32 + lane];
        ex0.x += pe[d] * w0.x; ex0.y += pe[d] * w0.y; ex0.z += pe[d] * w0.z; ex0.w += pe[d] * w0.w;
        ex1.x += pe[d] * w1.x; ex1.y += pe[d] * w1.y; ex1.z += pe[d] * w1.z; ex1.w += pe[d] * w1.w;
    }
    float4 sk0 = *reinterpret_cast<const float4*>(g_sk + (size_t)w * 256 + lane * 4);
    float4 sk1 = *reinterpret_cast<const float4*>(g_sk + (size_t)w * 256 + 128 + lane * 4);
    float4 o0, o1;
    o0.x = fmaxf((acc0.x + ex0.x) * inv + sk0.x, 0.f);
    o0.y = fmaxf((acc0.y + ex0.y) * inv + sk0.y, 0.f);
    o0.z = fmaxf((acc0.z + ex0.z) * inv + sk0.z, 0.f);
    o0.w = fmaxf((acc0.w + ex0.w) * inv + sk0.w, 0.f);
    o1.x = fmaxf((acc1.x + ex1.x) * inv + sk1.x, 0.f);
    o1.y = fmaxf((acc1.y + ex1.y) * inv + sk1.y, 0.f);
    o1.z = fmaxf((acc1.z + ex1.z) * inv + sk1.z, 0.f);
    o1.w = fmaxf((acc1.w + ex1.w) * inv + sk1.w, 0.f);
    *reinterpret_cast<float4*>(hout + (size_t)w * 256 + lane * 4) = o0;
    *reinterpret_cast<float4*>(hout + (size_t)w * 256 + 128 + lane * 4) = o1;
    uint2 hi, lo;
    split4(o0, &hi, &lo);
    *reinterpret_cast<uint2*>(g_hb + (size_t)w * KTOT + lane * 4) = hi;
    *reinterpret_cast<uint2*>(g_hb + (size_t)w * KTOT + 256 + lane * 4) = lo;
    split4(o1, &hi, &lo);
    *reinterpret_cast<uint2*>(g_hb + (size_t)w * KTOT + 128 + lane * 4) = hi;
    *reinterpret_cast<uint2*>(g_hb + (size_t)w * KTOT + 256 + 128 + lane * 4) = lo;
}

// ---------------- decoder ----------------
__global__ void dec_kernel(const float* __restrict__ Wd, const float* __restrict__ bd,
                           float* __restrict__ out) {
    __shared__ float sW[18 * 256];
    __shared__ float sb[18];
    for (int i = threadIdx.x; i < 18 * 256; i += blockDim.x) {
        int j = i / 18, o = i % 18;
        sW[o * 256 + j] = Wd[i];
    }
    if (threadIdx.x < 18) sb[threadIdx.x] = bd[threadIdx.x];
    __syncthreads();
    int w = (blockIdx.x * blockDim.x + threadIdx.x) >> 5;
    int lane = threadIdx.x & 31;
    if (w >= N_NODES) return;
    const float* h = g_h[1];
    float hr[8];
#pragma unroll
    for (int i = 0; i < 8; i++) hr[i] = h[(size_t)w * 256 + lane + 32 * i];
    for (int o = 0; o < 18; o++) {
        float p = 0.f;
#pragma unroll
        for (int i = 0; i < 8; i++) p += hr[i] * sW[o * 256 + lane + 32 * i];
#pragma unroll
        for (int off = 16; off; off >>= 1) p += __shfl_xor_sync(0xffffffffu, p, off);
        if (lane == 0) out[w * 18 + o] = p + sb[o];
    }
}

// ---------------- launch ----------------
extern "C" void kernel_launch(void* const* d_in, const int* in_sizes, int n_in,
                              void* d_out, int out_size) {
    const float* x = (const float*)d_in[0];
    const int* ei = (const int*)d_in[1];
    const float* edge_attr = (const float*)d_in[2];
    const float* t = (const float*)d_in[3];
    const float* s = (const float*)d_in[4];
    const float* W_emb = (const float*)d_in[5];
    const float* b_emb = (const float*)d_in[6];
    const float* W_t = (const float*)d_in[7];
    const float* b_t = (const float*)d_in[8];
    const float* W_s = (const float*)d_in[9];
    const float* b_s = (const float*)d_in[10];
    const float* W_f = (const float*)d_in[11];
    const float* b_f = (const float*)d_in[12];
    const float* ln_g = (const float*)d_in[13];
    const float* ln_b = (const float*)d_in[14];
    const float* Wq = (const float*)d_in[15];
    const float* bq = (const float*)d_in[16];
    const float* Wk = (const float*)d_in[17];
    const float* bk = (const float*)d_in[18];
    const float* Wv = (const float*)d_in[19];
    const float* bv = (const float*)d_in[20];
    const float* We = (const float*)d_in[21];
    const float* be = (const float*)d_in[22];
    const float* Wskip = (const float*)d_in[23];
    const float* bskip = (const float*)d_in[24];
    const float* W_dec = (const float*)d_in[25];
    const float* b_dec = (const float*)d_in[26];
    float* out = (float*)d_out;
    (void)in_sizes; (void)n_in; (void)out_size;

    wconv_kernel<<<dim3(8, 8, 20), 256>>>(Wq, Wk, Wv, Wskip);                        // 0
    fuse_kernel<<<52, 256>>>(W_emb, W_t, W_s, W_f, b_emb, b_t, b_s, b_f, bskip, be); // 1
    encoder_kernel<<<296, 256>>>(x, t, s, ln_g, ln_b);                               // 2

    dim3 ggrid(157, 2, 4);
    gemm_wb<<<ggrid, 256>>>(0, bq, bk, bv);                                          // 3 <- profiled

    zero_deg_kernel<<<NBLK, 256>>>();                   // 4
    hist_kernel<<<(N_EDGES + 255) / 256, 256>>>(ei);    // 5
    scanA_kernel<<<NBLK, 256>>>();                      // 6
    scanB_kernel<<<1, 1>>>();                           // 7
    scanC_kernel<<<NBLK, 256>>>();                      // 8
    scatter_kernel<<<(N_EDGES + 255) / 256, 256>>>(ei); // 9

    int attn_blocks = (N_NODES * 32 + 255) / 256;
    attn_kernel<<<attn_blocks, 256>>>(We + 0 * 2048, edge_attr, 0);                  // 10
    for (int L = 1; L < N_LAYERS; L++) {
        int pin = L & 1;
        gemm_wb<<<ggrid, 256>>>(L, bq, bk, bv);
        attn_kernel<<<attn_blocks, 256>>>(We + L * 2048, edge_attr, pin);
    }
    dec_kernel<<<attn_blocks, 256>>>(W_dec, b_dec, out);
}

// round 12
// speedup vs baseline: 1.4263x; 1.1760x over previous
#include <cuda_runtime.h>
#include <cuda_bf16.h>
#include <math.h>
#include <stdint.h>
#include <mma.h>

using namespace nvcuda;

#define N_NODES 20000
#define N_EDGES 640000
#define HID 256
#define NH (N_NODES * HID)
#define N_LAYERS 5
#define KTOT 512       // stored split K (hi | lo)
#define GKCH 32        // GEMM K elements per pipelined chunk
#define GNCH 24        // 3 segments x 8 chunks: (hi,hi) (lo,hi) (hi,lo)
#define GLDA 40        // gemm smem leading dim (bf16; 80B, 16B-multiple)
#define LDS_STAGE 68   // epilogue staging ld (floats; 272B, 16B-multiple)
#define NBLK 79        // ceil(20000/256)

// ---------------- scratch ----------------
__device__ float g_h[2][NH];
__device__ float g_q[NH], g_k[NH], g_v[NH], g_sk[NH];
__device__ __align__(256) __nv_bfloat16 g_hb[N_NODES * KTOT];            // A split [M, hi|lo]
__device__ __align__(256) __nv_bfloat16 g_Wb[4 * N_LAYERS * 256 * KTOT]; // B split [N, hi|lo]
__device__ float g_M[46 * HID];
__device__ float g_bias[HID];
__device__ float g_skbias[N_LAYERS * HID];
__device__ int g_deg[N_NODES];
__device__ int g_offs[N_NODES + 1];
__device__ int g_bsum[NBLK];
__device__ int g_cursor[N_NODES];
__device__ int g_ssrc[N_EDGES];
__device__ int g_seid[N_EDGES];

__device__ __forceinline__ void split_store(float v, __nv_bfloat16* hi_p, __nv_bfloat16* lo_p) {
    __nv_bfloat16 h = __float2bfloat16(v);
    *hi_p = h;
    *lo_p = __float2bfloat16(v - __bfloat162float(h));
}
__device__ __forceinline__ float dot4(float4 a, float4 b) {
    return a.x * b.x + a.y * b.y + a.z * b.z + a.w * b.w;
}
__device__ __forceinline__ void split4(float4 v, uint2* hi, uint2* lo) {
    __nv_bfloat16 hx = __float2bfloat16(v.x), hy = __float2bfloat16(v.y);
    __nv_bfloat16 hz = __float2bfloat16(v.z), hw = __float2bfloat16(v.w);
    __nv_bfloat162 h01 = __nv_bfloat162(hx, hy), h23 = __nv_bfloat162(hz, hw);
    hi->x = *reinterpret_cast<uint32_t*>(&h01);
    hi->y = *reinterpret_cast<uint32_t*>(&h23);
    __nv_bfloat162 l01 = __nv_bfloat162(__float2bfloat16(v.x - __bfloat162float(hx)),
                                        __float2bfloat16(v.y - __bfloat162float(hy)));
    __nv_bfloat162 l23 = __nv_bfloat162(__float2bfloat16(v.z - __bfloat162float(hz)),
                                        __float2bfloat16(v.w - __bfloat162float(hw)));
    lo->x = *reinterpret_cast<uint32_t*>(&l01);
    lo->y = *reinterpret_cast<uint32_t*>(&l23);
}
__device__ __forceinline__ void cp16(void* dst_smem, const void* src) {
    uint32_t d = (uint32_t)__cvta_generic_to_shared(dst_smem);
    asm volatile("cp.async.cg.shared.global [%0], [%1], 16;" :: "r"(d), "l"(src));
}
#define CP_COMMIT() asm volatile("cp.async.commit_group;" ::: "memory")
#define CP_WAIT1() asm volatile("cp.async.wait_group 1;" ::: "memory")
#define CP_WAIT0() asm volatile("cp.async.wait_group 0;" ::: "memory")

// ---------------- weight conversion: W[K,N] fp32 -> Wb[N, 512] bf16 (hi|lo) ----------------
__global__ void wconv_kernel(const float* __restrict__ Wq, const float* __restrict__ Wk,
                             const float* __restrict__ Wv, const float* __restrict__ Wsk) {
    __shared__ float s[32][33];
    int z = blockIdx.z;
    int w = z / N_LAYERS, l = z % N_LAYERS;
    const float* src = (w == 0) ? Wq : (w == 1) ? Wk : (w == 2) ? Wv : Wsk;
    src += l * 65536;
    __nv_bfloat16* dst = g_Wb + (size_t)z * 256 * KTOT;
    int k0 = blockIdx.x * 32, n0 = blockIdx.y * 32;
    int tx = threadIdx.x & 31, ty = threadIdx.x >> 5;
#pragma unroll
    for (int it = 0; it < 4; it++) {
        int r = ty + it * 8;
        s[r][tx] = src[(k0 + r) * 256 + n0 + tx];
    }
    __syncthreads();
#pragma unroll
    for (int it = 0; it < 4; it++) {
        int r = ty + it * 8;
        float v = s[tx][r];
        split_store(v, dst + (size_t)(n0 + r) * KTOT + k0 + tx,
                    dst + (size_t)(n0 + r) * KTOT + 256 + k0 + tx);
    }
}

// ---------------- fused encoder weights + skip-bias fold ----------------
__global__ void fuse_kernel(const float* __restrict__ W_emb, const float* __restrict__ W_t,
                            const float* __restrict__ W_s, const float* __restrict__ W_f,
                            const float* __restrict__ b_emb, const float* __restrict__ b_t,
                            const float* __restrict__ b_s, const float* __restrict__ b_f,
                            const float* __restrict__ bskip, const float* __restrict__ be) {
    int c = threadIdx.x;
    int r = blockIdx.x;
    if (r < 36) {
        float a = 0.f;
        for (int k = 0; k < 256; k++) a += W_emb[r * 256 + k] * W_f[k * 256 + c];
        g_M[r * 256 + c] = a;
    } else if (r < 40) {
        int rr = r - 36;
        float a = 0.f;
        for (int k = 0; k < 256; k++) a += W_t[rr * 256 + k] * W_f[(256 + k) * 256 + c];
        g_M[r * 256 + c] = a;
    } else if (r < 46) {
        int rr = r - 40;
        float a = 0.f;
        for (int k = 0; k < 256; k++) a += W_s[rr * 256 + k] * W_f[(512 + k) * 256 + c];
        g_M[r * 256 + c] = a;
    } else if (r == 46) {
        float a = b_f[c];
        for (int k = 0; k < 256; k++) {
            a += b_emb[k] * W_f[k * 256 + c];
            a += b_t[k] * W_f[(256 + k) * 256 + c];
            a += b_s[k] * W_f[(512 + k) * 256 + c];
        }
        g_bias[c] = a;
    } else {
        int l = r - 47;
        g_skbias[l * 256 + c] = bskip[l * 256 + c] + be[l * 256 + c];
    }
}

// ---------------- encoder ----------------
__global__ void encoder_kernel(const float* __restrict__ x, const float* __restrict__ t,
                               const float* __restrict__ s, const float* __restrict__ ln_g,
                               const float* __restrict__ ln_b) {
    __shared__ float sM[46 * 256];
    __shared__ float sb[256];
    __shared__ float sin_v[46];
    __shared__ float red[16];
    int tid = threadIdx.x;
    for (int i = tid; i < 46 * 256; i += 256) sM[i] = g_M[i];
    sb[tid] = g_bias[tid];
    float lg = ln_g[tid], lb = ln_b[tid];
    __syncthreads();
    for (int node = blockIdx.x; node < N_NODES; node += gridDim.x) {
        if (tid < 36) sin_v[tid] = x[node * 36 + tid];
        else if (tid < 40) sin_v[tid] = t[node * 4 + (tid - 36)];
        else if (tid < 46) sin_v[tid] = s[node * 6 + (tid - 40)];
        __syncthreads();
        float acc = sb[tid];
#pragma unroll
        for (int r = 0; r < 46; r++) acc += sin_v[r] * sM[r * 256 + tid];
        float ssum = acc, ssq = acc * acc;
#pragma unroll
        for (int o = 16; o; o >>= 1) {
            ssum += __shfl_xor_sync(0xffffffffu, ssum, o);
            ssq += __shfl_xor_sync(0xffffffffu, ssq, o);
        }
        if ((tid & 31) == 0) { red[tid >> 5] = ssum; red[8 + (tid >> 5)] = ssq; }
        __syncthreads();
        if (tid < 32) {
            float a = (tid < 8) ? red[tid] : 0.f;
            float b = (tid < 8) ? red[8 + tid] : 0.f;
#pragma unroll
            for (int o = 4; o; o >>= 1) {
                a += __shfl_xor_sync(0xffffffffu, a, o);
                b += __shfl_xor_sync(0xffffffffu, b, o);
            }
            if (tid == 0) { red[0] = a; red[1] = b; }
        }
        __syncthreads();
        float mu = red[0] * (1.f / 256.f);
        float var = red[1] * (1.f / 256.f) - mu * mu;
        float val = fmaxf((acc - mu) * rsqrtf(var + 1e-5f) * lg + lb, 0.f);
        g_h[0][node * 256 + tid] = val;
        split_store(val, g_hb + (size_t)node * KTOT + tid, g_hb + (size_t)node * KTOT + 256 + tid);
        __syncthreads();
    }
}

// ---------------- CSR build (3-phase scan) ----------------
__global__ void zero_deg_kernel() {
    int i = blockIdx.x * blockDim.x + threadIdx.x;
    if (i < N_NODES) g_deg[i] = 0;
}
__global__ void hist_kernel(const int* __restrict__ ei) {
    int e = blockIdx.x * blockDim.x + threadIdx.x;
    if (e < N_EDGES) atomicAdd(&g_deg[ei[N_EDGES + e]], 1);
}
__global__ void scanA_kernel() {
    __shared__ int wsum[8];
    int b = blockIdx.x, tid = threadIdx.x;
    int i = b * 256 + tid;
    int lane = tid & 31, wid = tid >> 5;
    int v = (i < N_NODES) ? g_deg[i] : 0;
    int x = v;
#pragma unroll
    for (int o = 1; o < 32; o <<= 1) {
        int y = __shfl_up_sync(0xffffffffu, x, o);
        if (lane >= o) x += y;
    }
    if (lane == 31) wsum[wid] = x;
    __syncthreads();
    if (wid == 0) {
        int s = (lane < 8) ? wsum[lane] : 0;
#pragma unroll
        for (int o = 1; o < 8; o <<= 1) {
            int y = __shfl_up_sync(0xffffffffu, s, o);
            if (lane >= o) s += y;
        }
        if (lane < 8) wsum[lane] = s;
    }
    __syncthreads();
    int base = (wid > 0) ? wsum[wid - 1] : 0;
    int incl = base + x;
    if (i < N_NODES) g_offs[i] = incl - v;
    if (tid == 255) g_bsum[b] = incl;
}
__global__ void scanB_kernel() {
    int total = 0;
    for (int b = 0; b < NBLK; b++) {
        int t = g_bsum[b];
        g_bsum[b] = total;
        total += t;
    }
    g_offs[N_NODES] = total;
}
__global__ void scanC_kernel() {
    int i = blockIdx.x * 256 + threadIdx.x;
    if (i < N_NODES) {
        int o = g_offs[i] + g_bsum[blockIdx.x];
        g_offs[i] = o;
        g_cursor[i] = o;
    }
}
__global__ void scatter_kernel(const int* __restrict__ ei) {
    int e = blockIdx.x * blockDim.x + threadIdx.x;
    if (e < N_EDGES) {
        int d = ei[N_EDGES + e];
        int pos = atomicAdd(&g_cursor[d], 1);
        g_ssrc[pos] = ei[e];
        g_seid[pos] = e;
    }
}

// ---------------- bf16 wmma GEMM, 128x128 tile, cp.async double-buffered ----------------
__global__ void __launch_bounds__(256)
gemm_wb(int layer, const float* __restrict__ bq_, const float* __restrict__ bk_,
        const float* __restrict__ bv_) {
    __shared__ __align__(16) __nv_bfloat16 smem_all[2 * 2 * 128 * GLDA];
    __shared__ float sbias[128];

    int tid = threadIdx.x;
    int wid = tid >> 5, lane = tid & 31;
    int wr = wid >> 1, wc = wid & 1;
    int w = blockIdx.z;
    int row0 = blockIdx.x * 128;
    int colblk = blockIdx.y * 128;
    int col0 = colblk + wc * 64;

    const __nv_bfloat16* Bsrc = g_Wb + ((size_t)w * N_LAYERS + layer) * 256 * KTOT;
    float* C;
    const float* bias;
    if (w == 0) { C = g_q; bias = bq_ + layer * 256; }
    else if (w == 1) { C = g_k; bias = bk_ + layer * 256; }
    else if (w == 2) { C = g_v; bias = bv_ + layer * 256; }
    else { C = g_sk; bias = g_skbias + layer * 256; }

    if (tid < 128) sbias[tid] = bias[colblk + tid];

    int l0 = tid, l1 = tid + 256;
    int ar0 = l0 >> 2, ak0 = (l0 & 3) * 8;
    int ar1 = l1 >> 2, ak1 = (l1 & 3) * 8;
    int gr0 = row0 + ar0; if (gr0 >= N_NODES) gr0 = N_NODES - 1;
    int gr1 = row0 + ar1; if (gr1 >= N_NODES) gr1 = N_NODES - 1;

    wmma::fragment<wmma::accumulator, 16, 16, 16, float> acc[2][4];
#pragma unroll
    for (int m = 0; m < 2; m++)
#pragma unroll
        for (int n = 0; n < 4; n++) wmma::fill_fragment(acc[m][n], 0.f);

    auto issue = [&](int c, int buf) {
        int seg = c >> 3, cc = c & 7;
        int aoff = (seg == 1) ? 256 : 0;
        int boff = (seg == 2) ? 256 : 0;
        __nv_bfloat16* As = smem_all + buf * 2 * 128 * GLDA;
        __nv_bfloat16* Bs = As + 128 * GLDA;
        cp16(As + ar0 * GLDA + ak0, g_hb + (size_t)gr0 * KTOT + aoff + cc * GKCH + ak0);
        cp16(As + ar1 * GLDA + ak1, g_hb + (size_t)gr1 * KTOT + aoff + cc * GKCH + ak1);
        cp16(Bs + ar0 * GLDA + ak0, Bsrc + (size_t)(colblk + ar0) * KTOT + boff + cc * GKCH + ak0);
        cp16(Bs + ar1 * GLDA + ak1, Bsrc + (size_t)(colblk + ar1) * KTOT + boff + cc * GKCH + ak1);
        CP_COMMIT();
    };

    issue(0, 0);
    for (int c = 0; c < GNCH; c++) {
        if (c + 1 < GNCH) { issue(c + 1, (c + 1) & 1); CP_WAIT1(); }
        else { CP_WAIT0(); }
        __syncthreads();
        __nv_bfloat16* As = smem_all + (c & 1) * 2 * 128 * GLDA;
        __nv_bfloat16* Bs = As + 128 * GLDA;
#pragma unroll
        for (int ks = 0; ks < 2; ks++) {
            wmma::fragment<wmma::matrix_a, 16, 16, 16, __nv_bfloat16, wmma::row_major> af[2];
            wmma::fragment<wmma::matrix_b, 16, 16, 16, __nv_bfloat16, wmma::col_major> bf[4];
#pragma unroll
            for (int m = 0; m < 2; m++)
                wmma::load_matrix_sync(af[m], As + (wr * 32 + m * 16) * GLDA + ks * 16, GLDA);
#pragma unroll
            for (int n = 0; n < 4; n++)
                wmma::load_matrix_sync(bf[n], Bs + (wc * 64 + n * 16) * GLDA + ks * 16, GLDA);
#pragma unroll
            for (int m = 0; m < 2; m++)
#pragma unroll
                for (int n = 0; n < 4; n++) wmma::mma_sync(acc[m][n], af[m], bf[n], acc[m][n]);
        }
        __syncthreads();
    }

    float* stage = reinterpret_cast<float*>(smem_all) + wid * 16 * LDS_STAGE;
#pragma unroll
    for (int m = 0; m < 2; m++) {
        __syncwarp();
#pragma unroll
        for (int n = 0; n < 4; n++)
            wmma::store_matrix_sync(stage + n * 16, acc[m][n], LDS_STAGE, wmma::mem_row_major);
        __syncwarp();
        int rbase = row0 + wr * 32 + m * 16;
#pragma unroll
        for (int i = lane; i < 16 * 64; i += 32) {
            int r = i >> 6, cc2 = i & 63;
            int gr = rbase + r;
            if (gr < N_NODES)
                C[(size_t)gr * 256 + col0 + cc2] = stage[r * LDS_STAGE + cc2] + sbias[wc * 64 + cc2];
        }
        __syncwarp();
    }
}

// ---------------- attention: lane-owned edge features, occ 4 ----------------
// lane d<8 owns qwe[d], e[d], pea[d]; alpha edge-term folds into the warp reduction.
__global__ void __launch_bounds__(256, 4)
attn_kernel(const float* __restrict__ We_l, const float* __restrict__ edge_attr, int pin) {
    __shared__ float sWe[8 * 256];
    for (int i = threadIdx.x; i < 2048; i += blockDim.x) sWe[i] = We_l[i];
    __syncthreads();
    const float4* sWe4 = reinterpret_cast<const float4*>(sWe);
    int w = (blockIdx.x * blockDim.x + threadIdx.x) >> 5;
    int lane = threadIdx.x & 31;
    if (w >= N_NODES) return;
    float* hout = g_h[pin ^ 1];

    float4 q0 = *reinterpret_cast<const float4*>(g_q + (size_t)w * 256 + lane * 4);
    float4 q1 = *reinterpret_cast<const float4*>(g_q + (size_t)w * 256 + 128 + lane * 4);

    // qwe_own: lane d<8 holds dot(q, We[d,:]); other lanes 0
    float qwe_own = 0.f;
#pragma unroll
    for (int d = 0; d < 8; d++) {
        float p = dot4(q0, sWe4[d * 64 + lane]) + dot4(q1, sWe4[d * 64 + 32 + lane]);
#pragma unroll
        for (int o = 16; o; o >>= 1) p += __shfl_xor_sync(0xffffffffu, p, o);
        if (lane == d) qwe_own = p;
    }

    float m = -INFINITY, den = 0.f;
    float4 acc0 = make_float4(0, 0, 0, 0), acc1 = make_float4(0, 0, 0, 0);
    float pea_own = 0.f;
    int beg = g_offs[w], end = g_offs[w + 1];
    const float* ea_base = edge_attr;
    for (int t = beg; t < end; t++) {
        int src = g_ssrc[t];
        int eid = g_seid[t];
        const float4* kr = reinterpret_cast<const float4*>(g_k + (size_t)src * 256);
        const float4* vr = reinterpret_cast<const float4*>(g_v + (size_t)src * 256);
        float4 k0 = kr[lane], k1 = kr[32 + lane];
        float4 v0 = vr[lane], v1 = vr[32 + lane];
        float e_own = (lane < 8) ? __ldg(ea_base + (size_t)eid * 8 + lane) : 0.f;

        // partial includes this lane's qwe[d]*e[d]; reduction sums dot + edge term
        float partial = dot4(q0, k0) + dot4(q1, k1) + qwe_own * e_own;
#pragma unroll
        for (int o = 16; o; o >>= 1) partial += __shfl_xor_sync(0xffffffffu, partial, o);
        float alpha = partial * 0.0625f;
        float mn = fmaxf(m, alpha);
        float corr = __expf(m - mn);
        float p = __expf(alpha - mn);
        m = mn;
        den = den * corr + p;
        acc0.x = acc0.x * corr + p * v0.x; acc0.y = acc0.y * corr + p * v0.y;
        acc0.z = acc0.z * corr + p * v0.z; acc0.w = acc0.w * corr + p * v0.w;
        acc1.x = acc1.x * corr + p * v1.x; acc1.y = acc1.y * corr + p * v1.y;
        acc1.z = acc1.z * corr + p * v1.z; acc1.w = acc1.w * corr + p * v1.w;
        pea_own = pea_own * corr + p * e_own;
    }
    float inv = 1.f / (den + 1e-16f);
    // broadcast pea[d] from lanes 0..7
    float pe[8];
#pragma unroll
    for (int d = 0; d < 8; d++) pe[d] = __shfl_sync(0xffffffffu, pea_own, d);
    float4 ex0 = make_float4(0, 0, 0, 0), ex1 = make_float4(0, 0, 0, 0);
#pragma unroll
    for (int d = 0; d < 8; d++) {
        float4 w0 = sWe4[d * 64 + lane], w1 = sWe4[d * 64 + 32 + lane];
        ex0.x += pe[d] * w0.x; ex0.y += pe[d] * w0.y; ex0.z += pe[d] * w0.z; ex0.w += pe[d] * w0.w;
        ex1.x += pe[d] * w1.x; ex1.y += pe[d] * w1.y; ex1.z += pe[d] * w1.z; ex1.w += pe[d] * w1.w;
    }
    float4 sk0 = *reinterpret_cast<const float4*>(g_sk + (size_t)w * 256 + lane * 4);
    float4 sk1 = *reinterpret_cast<const float4*>(g_sk + (size_t)w * 256 + 128 + lane * 4);
    float4 o0, o1;
    o0.x = fmaxf((acc0.x + ex0.x) * inv + sk0.x, 0.f);
    o0.y = fmaxf((acc0.y + ex0.y) * inv + sk0.y, 0.f);
    o0.z = fmaxf((acc0.z + ex0.z) * inv + sk0.z, 0.f);
    o0.w = fmaxf((acc0.w + ex0.w) * inv + sk0.w, 0.f);
    o1.x = fmaxf((acc1.x + ex1.x) * inv + sk1.x, 0.f);
    o1.y = fmaxf((acc1.y + ex1.y) * inv + sk1.y, 0.f);
    o1.z = fmaxf((acc1.z + ex1.z) * inv + sk1.z, 0.f);
    o1.w = fmaxf((acc1.w + ex1.w) * inv + sk1.w, 0.f);
    *reinterpret_cast<float4*>(hout + (size_t)w * 256 + lane * 4) = o0;
    *reinterpret_cast<float4*>(hout + (size_t)w * 256 + 128 + lane * 4) = o1;
    uint2 hi, lo;
    split4(o0, &hi, &lo);
    *reinterpret_cast<uint2*>(g_hb + (size_t)w * KTOT + lane * 4) = hi;
    *reinterpret_cast<uint2*>(g_hb + (size_t)w * KTOT + 256 + lane * 4) = lo;
    split4(o1, &hi, &lo);
    *reinterpret_cast<uint2*>(g_hb + (size_t)w * KTOT + 128 + lane * 4) = hi;
    *reinterpret_cast<uint2*>(g_hb + (size_t)w * KTOT + 256 + 128 + lane * 4) = lo;
}

// ---------------- decoder ----------------
__global__ void dec_kernel(const float* __restrict__ Wd, const float* __restrict__ bd,
                           float* __restrict__ out) {
    __shared__ float sW[18 * 256];
    __shared__ float sb[18];
    for (int i = threadIdx.x; i < 18 * 256; i += blockDim.x) {
        int j = i / 18, o = i % 18;
        sW[o * 256 + j] = Wd[i];
    }
    if (threadIdx.x < 18) sb[threadIdx.x] = bd[threadIdx.x];
    __syncthreads();
    int w = (blockIdx.x * blockDim.x + threadIdx.x) >> 5;
    int lane = threadIdx.x & 31;
    if (w >= N_NODES) return;
    const float* h = g_h[1];
    float hr[8];
#pragma unroll
    for (int i = 0; i < 8; i++) hr[i] = h[(size_t)w * 256 + lane + 32 * i];
    for (int o = 0; o < 18; o++) {
        float p = 0.f;
#pragma unroll
        for (int i = 0; i < 8; i++) p += hr[i] * sW[o * 256 + lane + 32 * i];
#pragma unroll
        for (int off = 16; off; off >>= 1) p += __shfl_xor_sync(0xffffffffu, p, off);
        if (lane == 0) out[w * 18 + o] = p + sb[o];
    }
}

// ---------------- launch ----------------
extern "C" void kernel_launch(void* const* d_in, const int* in_sizes, int n_in,
                              void* d_out, int out_size) {
    const float* x = (const float*)d_in[0];
    const int* ei = (const int*)d_in[1];
    const float* edge_attr = (const float*)d_in[2];
    const float* t = (const float*)d_in[3];
    const float* s = (const float*)d_in[4];
    const float* W_emb = (const float*)d_in[5];
    const float* b_emb = (const float*)d_in[6];
    const float* W_t = (const float*)d_in[7];
    const float* b_t = (const float*)d_in[8];
    const float* W_s = (const float*)d_in[9];
    const float* b_s = (const float*)d_in[10];
    const float* W_f = (const float*)d_in[11];
    const float* b_f = (const float*)d_in[12];
    const float* ln_g = (const float*)d_in[13];
    const float* ln_b = (const float*)d_in[14];
    const float* Wq = (const float*)d_in[15];
    const float* bq = (const float*)d_in[16];
    const float* Wk = (const float*)d_in[17];
    const float* bk = (const float*)d_in[18];
    const float* Wv = (const float*)d_in[19];
    const float* bv = (const float*)d_in[20];
    const float* We = (const float*)d_in[21];
    const float* be = (const float*)d_in[22];
    const float* Wskip = (const float*)d_in[23];
    const float* bskip = (const float*)d_in[24];
    const float* W_dec = (const float*)d_in[25];
    const float* b_dec = (const float*)d_in[26];
    float* out = (float*)d_out;
    (void)in_sizes; (void)n_in; (void)out_size;

    wconv_kernel<<<dim3(8, 8, 20), 256>>>(Wq, Wk, Wv, Wskip);                        // 0
    fuse_kernel<<<52, 256>>>(W_emb, W_t, W_s, W_f, b_emb, b_t, b_s, b_f, bskip, be); // 1
    encoder_kernel<<<296, 256>>>(x, t, s, ln_g, ln_b);                               // 2

    dim3 ggrid(157, 2, 4);
    gemm_wb<<<ggrid, 256>>>(0, bq, bk, bv);                                          // 3 <- profiled

    zero_deg_kernel<<<NBLK, 256>>>();                   // 4
    hist_kernel<<<(N_EDGES + 255) / 256, 256>>>(ei);    // 5
    scanA_kernel<<<NBLK, 256>>>();                      // 6
    scanB_kernel<<<1, 1>>>();                           // 7
    scanC_kernel<<<NBLK, 256>>>();                      // 8
    scatter_kernel<<<(N_EDGES + 255) / 256, 256>>>(ei); // 9

    int attn_blocks = (N_NODES * 32 + 255) / 256;
    attn_kernel<<<attn_blocks, 256>>>(We + 0 * 2048, edge_attr, 0);                  // 10
    for (int L = 1; L < N_LAYERS; L++) {
        int pin = L & 1;
        gemm_wb<<<ggrid, 256>>>(L, bq, bk, bv);
        attn_kernel<<<attn_blocks, 256>>>(We + L * 2048, edge_attr, pin);
    }
    dec_kernel<<<attn_blocks, 256>>>(W_dec, b_dec, out);
}

// round 13
// speedup vs baseline: 1.4552x; 1.0202x over previous
#include <cuda_runtime.h>
#include <cuda_bf16.h>
#include <cuda_fp16.h>
#include <math.h>
#include <stdint.h>
#include <mma.h>

using namespace nvcuda;

#define N_NODES 20000
#define N_EDGES 640000
#define HID 256
#define NH (N_NODES * HID)
#define N_LAYERS 5
#define KTOT 512       // stored split K (hi | lo)
#define GKCH 32        // GEMM K elements per pipelined chunk
#define GNCH 24        // 3 segments x 8 chunks: (hi,hi) (lo,hi) (hi,lo)
#define GLDA 40        // gemm smem leading dim (bf16; 80B, 16B-multiple)
#define LDS_STAGE 68   // epilogue staging ld (floats; 272B, 16B-multiple)
#define NBLK 79        // ceil(20000/256)

// ---------------- scratch ----------------
__device__ float g_h[2][NH];
__device__ float g_q[NH], g_k[NH], g_v[NH], g_sk[NH];
__device__ __align__(16) __half g_kh[NH];                                // K in fp16 for attention gather
__device__ __align__(256) __nv_bfloat16 g_hb[N_NODES * KTOT];            // A split [M, hi|lo]
__device__ __align__(256) __nv_bfloat16 g_Wb[4 * N_LAYERS * 256 * KTOT]; // B split [N, hi|lo]
__device__ float g_M[46 * HID];
__device__ float g_bias[HID];
__device__ float g_skbias[N_LAYERS * HID];
__device__ int g_deg[N_NODES];
__device__ int g_offs[N_NODES + 1];
__device__ int g_bsum[NBLK];
__device__ int g_cursor[N_NODES];
__device__ int g_ssrc[N_EDGES];
__device__ int g_seid[N_EDGES];

__device__ __forceinline__ void split_store(float v, __nv_bfloat16* hi_p, __nv_bfloat16* lo_p) {
    __nv_bfloat16 h = __float2bfloat16(v);
    *hi_p = h;
    *lo_p = __float2bfloat16(v - __bfloat162float(h));
}
__device__ __forceinline__ float dot4(float4 a, float4 b) {
    return a.x * b.x + a.y * b.y + a.z * b.z + a.w * b.w;
}
__device__ __forceinline__ void split4(float4 v, uint2* hi, uint2* lo) {
    __nv_bfloat16 hx = __float2bfloat16(v.x), hy = __float2bfloat16(v.y);
    __nv_bfloat16 hz = __float2bfloat16(v.z), hw = __float2bfloat16(v.w);
    __nv_bfloat162 h01 = __nv_bfloat162(hx, hy), h23 = __nv_bfloat162(hz, hw);
    hi->x = *reinterpret_cast<uint32_t*>(&h01);
    hi->y = *reinterpret_cast<uint32_t*>(&h23);
    __nv_bfloat162 l01 = __nv_bfloat162(__float2bfloat16(v.x - __bfloat162float(hx)),
                                        __float2bfloat16(v.y - __bfloat162float(hy)));
    __nv_bfloat162 l23 = __nv_bfloat162(__float2bfloat16(v.z - __bfloat162float(hz)),
                                        __float2bfloat16(v.w - __bfloat162float(hw)));
    lo->x = *reinterpret_cast<uint32_t*>(&l01);
    lo->y = *reinterpret_cast<uint32_t*>(&l23);
}
__device__ __forceinline__ void cp16(void* dst_smem, const void* src) {
    uint32_t d = (uint32_t)__cvta_generic_to_shared(dst_smem);
    asm volatile("cp.async.cg.shared.global [%0], [%1], 16;" :: "r"(d), "l"(src));
}
#define CP_COMMIT() asm volatile("cp.async.commit_group;" ::: "memory")
#define CP_WAIT1() asm volatile("cp.async.wait_group 1;" ::: "memory")
#define CP_WAIT0() asm volatile("cp.async.wait_group 0;" ::: "memory")

// ---------------- weight conversion: W[K,N] fp32 -> Wb[N, 512] bf16 (hi|lo) ----------------
__global__ void wconv_kernel(const float* __restrict__ Wq, const float* __restrict__ Wk,
                             const float* __restrict__ Wv, const float* __restrict__ Wsk) {
    __shared__ float s[32][33];
    int z = blockIdx.z;
    int w = z / N_LAYERS, l = z % N_LAYERS;
    const float* src = (w == 0) ? Wq : (w == 1) ? Wk : (w == 2) ? Wv : Wsk;
    src += l * 65536;
    __nv_bfloat16* dst = g_Wb + (size_t)z * 256 * KTOT;
    int k0 = blockIdx.x * 32, n0 = blockIdx.y * 32;
    int tx = threadIdx.x & 31, ty = threadIdx.x >> 5;
#pragma unroll
    for (int it = 0; it < 4; it++) {
        int r = ty + it * 8;
        s[r][tx] = src[(k0 + r) * 256 + n0 + tx];
    }
    __syncthreads();
#pragma unroll
    for (int it = 0; it < 4; it++) {
        int r = ty + it * 8;
        float v = s[tx][r];
        split_store(v, dst + (size_t)(n0 + r) * KTOT + k0 + tx,
                    dst + (size_t)(n0 + r) * KTOT + 256 + k0 + tx);
    }
}

// ---------------- fused encoder weights + skip-bias fold ----------------
__global__ void fuse_kernel(const float* __restrict__ W_emb, const float* __restrict__ W_t,
                            const float* __restrict__ W_s, const float* __restrict__ W_f,
                            const float* __restrict__ b_emb, const float* __restrict__ b_t,
                            const float* __restrict__ b_s, const float* __restrict__ b_f,
                            const float* __restrict__ bskip, const float* __restrict__ be) {
    int c = threadIdx.x;
    int r = blockIdx.x;
    if (r < 36) {
        float a = 0.f;
        for (int k = 0; k < 256; k++) a += W_emb[r * 256 + k] * W_f[k * 256 + c];
        g_M[r * 256 + c] = a;
    } else if (r < 40) {
        int rr = r - 36;
        float a = 0.f;
        for (int k = 0; k < 256; k++) a += W_t[rr * 256 + k] * W_f[(256 + k) * 256 + c];
        g_M[r * 256 + c] = a;
    } else if (r < 46) {
        int rr = r - 40;
        float a = 0.f;
        for (int k = 0; k < 256; k++) a += W_s[rr * 256 + k] * W_f[(512 + k) * 256 + c];
        g_M[r * 256 + c] = a;
    } else if (r == 46) {
        float a = b_f[c];
        for (int k = 0; k < 256; k++) {
            a += b_emb[k] * W_f[k * 256 + c];
            a += b_t[k] * W_f[(256 + k) * 256 + c];
            a += b_s[k] * W_f[(512 + k) * 256 + c];
        }
        g_bias[c] = a;
    } else {
        int l = r - 47;
        g_skbias[l * 256 + c] = bskip[l * 256 + c] + be[l * 256 + c];
    }
}

// ---------------- encoder ----------------
__global__ void encoder_kernel(const float* __restrict__ x, const float* __restrict__ t,
                               const float* __restrict__ s, const float* __restrict__ ln_g,
                               const float* __restrict__ ln_b) {
    __shared__ float sM[46 * 256];
    __shared__ float sb[256];
    __shared__ float sin_v[46];
    __shared__ float red[16];
    int tid = threadIdx.x;
    for (int i = tid; i < 46 * 256; i += 256) sM[i] = g_M[i];
    sb[tid] = g_bias[tid];
    float lg = ln_g[tid], lb = ln_b[tid];
    __syncthreads();
    for (int node = blockIdx.x; node < N_NODES; node += gridDim.x) {
        if (tid < 36) sin_v[tid] = x[node * 36 + tid];
        else if (tid < 40) sin_v[tid] = t[node * 4 + (tid - 36)];
        else if (tid < 46) sin_v[tid] = s[node * 6 + (tid - 40)];
        __syncthreads();
        float acc = sb[tid];
#pragma unroll
        for (int r = 0; r < 46; r++) acc += sin_v[r] * sM[r * 256 + tid];
        float ssum = acc, ssq = acc * acc;
#pragma unroll
        for (int o = 16; o; o >>= 1) {
            ssum += __shfl_xor_sync(0xffffffffu, ssum, o);
            ssq += __shfl_xor_sync(0xffffffffu, ssq, o);
        }
        if ((tid & 31) == 0) { red[tid >> 5] = ssum; red[8 + (tid >> 5)] = ssq; }
        __syncthreads();
        if (tid < 32) {
            float a = (tid < 8) ? red[tid] : 0.f;
            float b = (tid < 8) ? red[8 + tid] : 0.f;
#pragma unroll
            for (int o = 4; o; o >>= 1) {
                a += __shfl_xor_sync(0xffffffffu, a, o);
                b += __shfl_xor_sync(0xffffffffu, b, o);
            }
            if (tid == 0) { red[0] = a; red[1] = b; }
        }
        __syncthreads();
        float mu = red[0] * (1.f / 256.f);
        float var = red[1] * (1.f / 256.f) - mu * mu;
        float val = fmaxf((acc - mu) * rsqrtf(var + 1e-5f) * lg + lb, 0.f);
        g_h[0][node * 256 + tid] = val;
        split_store(val, g_hb + (size_t)node * KTOT + tid, g_hb + (size_t)node * KTOT + 256 + tid);
        __syncthreads();
    }
}

// ---------------- CSR build (3-phase scan) ----------------
__global__ void zero_deg_kernel() {
    int i = blockIdx.x * blockDim.x + threadIdx.x;
    if (i < N_NODES) g_deg[i] = 0;
}
__global__ void hist_kernel(const int* __restrict__ ei) {
    int e = blockIdx.x * blockDim.x + threadIdx.x;
    if (e < N_EDGES) atomicAdd(&g_deg[ei[N_EDGES + e]], 1);
}
__global__ void scanA_kernel() {
    __shared__ int wsum[8];
    int b = blockIdx.x, tid = threadIdx.x;
    int i = b * 256 + tid;
    int lane = tid & 31, wid = tid >> 5;
    int v = (i < N_NODES) ? g_deg[i] : 0;
    int x = v;
#pragma unroll
    for (int o = 1; o < 32; o <<= 1) {
        int y = __shfl_up_sync(0xffffffffu, x, o);
        if (lane >= o) x += y;
    }
    if (lane == 31) wsum[wid] = x;
    __syncthreads();
    if (wid == 0) {
        int s = (lane < 8) ? wsum[lane] : 0;
#pragma unroll
        for (int o = 1; o < 8; o <<= 1) {
            int y = __shfl_up_sync(0xffffffffu, s, o);
            if (lane >= o) s += y;
        }
        if (lane < 8) wsum[lane] = s;
    }
    __syncthreads();
    int base = (wid > 0) ? wsum[wid - 1] : 0;
    int incl = base + x;
    if (i < N_NODES) g_offs[i] = incl - v;
    if (tid == 255) g_bsum[b] = incl;
}
__global__ void scanB_kernel() {
    int total = 0;
    for (int b = 0; b < NBLK; b++) {
        int t = g_bsum[b];
        g_bsum[b] = total;
        total += t;
    }
    g_offs[N_NODES] = total;
}
__global__ void scanC_kernel() {
    int i = blockIdx.x * 256 + threadIdx.x;
    if (i < N_NODES) {
        int o = g_offs[i] + g_bsum[blockIdx.x];
        g_offs[i] = o;
        g_cursor[i] = o;
    }
}
__global__ void scatter_kernel(const int* __restrict__ ei) {
    int e = blockIdx.x * blockDim.x + threadIdx.x;
    if (e < N_EDGES) {
        int d = ei[N_EDGES + e];
        int pos = atomicAdd(&g_cursor[d], 1);
        g_ssrc[pos] = ei[e];
        g_seid[pos] = e;
    }
}

// ---------------- bf16 wmma GEMM, 128x128 tile, cp.async double-buffered ----------------
// w==1 (K GEMM) additionally stores fp16 copy for the attention gather.
__global__ void __launch_bounds__(256)
gemm_wb(int layer, const float* __restrict__ bq_, const float* __restrict__ bk_,
        const float* __restrict__ bv_) {
    __shared__ __align__(16) __nv_bfloat16 smem_all[2 * 2 * 128 * GLDA];
    __shared__ float sbias[128];

    int tid = threadIdx.x;
    int wid = tid >> 5, lane = tid & 31;
    int wr = wid >> 1, wc = wid & 1;
    int w = blockIdx.z;
    int row0 = blockIdx.x * 128;
    int colblk = blockIdx.y * 128;
    int col0 = colblk + wc * 64;

    const __nv_bfloat16* Bsrc = g_Wb + ((size_t)w * N_LAYERS + layer) * 256 * KTOT;
    float* C;
    const float* bias;
    if (w == 0) { C = g_q; bias = bq_ + layer * 256; }
    else if (w == 1) { C = g_k; bias = bk_ + layer * 256; }
    else if (w == 2) { C = g_v; bias = bv_ + layer * 256; }
    else { C = g_sk; bias = g_skbias + layer * 256; }

    if (tid < 128) sbias[tid] = bias[colblk + tid];

    int l0 = tid, l1 = tid + 256;
    int ar0 = l0 >> 2, ak0 = (l0 & 3) * 8;
    int ar1 = l1 >> 2, ak1 = (l1 & 3) * 8;
    int gr0 = row0 + ar0; if (gr0 >= N_NODES) gr0 = N_NODES - 1;
    int gr1 = row0 + ar1; if (gr1 >= N_NODES) gr1 = N_NODES - 1;

    wmma::fragment<wmma::accumulator, 16, 16, 16, float> acc[2][4];
#pragma unroll
    for (int m = 0; m < 2; m++)
#pragma unroll
        for (int n = 0; n < 4; n++) wmma::fill_fragment(acc[m][n], 0.f);

    auto issue = [&](int c, int buf) {
        int seg = c >> 3, cc = c & 7;
        int aoff = (seg == 1) ? 256 : 0;
        int boff = (seg == 2) ? 256 : 0;
        __nv_bfloat16* As = smem_all + buf * 2 * 128 * GLDA;
        __nv_bfloat16* Bs = As + 128 * GLDA;
        cp16(As + ar0 * GLDA + ak0, g_hb + (size_t)gr0 * KTOT + aoff + cc * GKCH + ak0);
        cp16(As + ar1 * GLDA + ak1, g_hb + (size_t)gr1 * KTOT + aoff + cc * GKCH + ak1);
        cp16(Bs + ar0 * GLDA + ak0, Bsrc + (size_t)(colblk + ar0) * KTOT + boff + cc * GKCH + ak0);
        cp16(Bs + ar1 * GLDA + ak1, Bsrc + (size_t)(colblk + ar1) * KTOT + boff + cc * GKCH + ak1);
        CP_COMMIT();
    };

    issue(0, 0);
    for (int c = 0; c < GNCH; c++) {
        if (c + 1 < GNCH) { issue(c + 1, (c + 1) & 1); CP_WAIT1(); }
        else { CP_WAIT0(); }
        __syncthreads();
        __nv_bfloat16* As = smem_all + (c & 1) * 2 * 128 * GLDA;
        __nv_bfloat16* Bs = As + 128 * GLDA;
#pragma unroll
        for (int ks = 0; ks < 2; ks++) {
            wmma::fragment<wmma::matrix_a, 16, 16, 16, __nv_bfloat16, wmma::row_major> af[2];
            wmma::fragment<wmma::matrix_b, 16, 16, 16, __nv_bfloat16, wmma::col_major> bf[4];
#pragma unroll
            for (int m = 0; m < 2; m++)
                wmma::load_matrix_sync(af[m], As + (wr * 32 + m * 16) * GLDA + ks * 16, GLDA);
#pragma unroll
            for (int n = 0; n < 4; n++)
                wmma::load_matrix_sync(bf[n], Bs + (wc * 64 + n * 16) * GLDA + ks * 16, GLDA);
#pragma unroll
            for (int m = 0; m < 2; m++)
#pragma unroll
                for (int n = 0; n < 4; n++) wmma::mma_sync(acc[m][n], af[m], bf[n], acc[m][n]);
        }
        __syncthreads();
    }

    float* stage = reinterpret_cast<float*>(smem_all) + wid * 16 * LDS_STAGE;
#pragma unroll
    for (int m = 0; m < 2; m++) {
        __syncwarp();
#pragma unroll
        for (int n = 0; n < 4; n++)
            wmma::store_matrix_sync(stage + n * 16, acc[m][n], LDS_STAGE, wmma::mem_row_major);
        __syncwarp();
        int rbase = row0 + wr * 32 + m * 16;
#pragma unroll
        for (int i = lane; i < 16 * 64; i += 32) {
            int r = i >> 6, cc2 = i & 63;
            int gr = rbase + r;
            if (gr < N_NODES) {
                float val = stage[r * LDS_STAGE + cc2] + sbias[wc * 64 + cc2];
                size_t idx = (size_t)gr * 256 + col0 + cc2;
                C[idx] = val;
                if (w == 1) g_kh[idx] = __float2half(val);
            }
        }
        __syncwarp();
    }
}

// ---------------- attention: lane-owned edge features, fp16 K gather, occ 4 ----------------
__global__ void __launch_bounds__(256, 4)
attn_kernel(const float* __restrict__ We_l, const float* __restrict__ edge_attr, int pin) {
    __shared__ float sWe[8 * 256];
    for (int i = threadIdx.x; i < 2048; i += blockDim.x) sWe[i] = We_l[i];
    __syncthreads();
    const float4* sWe4 = reinterpret_cast<const float4*>(sWe);
    int w = (blockIdx.x * blockDim.x + threadIdx.x) >> 5;
    int lane = threadIdx.x & 31;
    if (w >= N_NODES) return;
    float* hout = g_h[pin ^ 1];

    float4 q0 = *reinterpret_cast<const float4*>(g_q + (size_t)w * 256 + lane * 4);
    float4 q1 = *reinterpret_cast<const float4*>(g_q + (size_t)w * 256 + 128 + lane * 4);

    float qwe_own = 0.f;
#pragma unroll
    for (int d = 0; d < 8; d++) {
        float p = dot4(q0, sWe4[d * 64 + lane]) + dot4(q1, sWe4[d * 64 + 32 + lane]);
#pragma unroll
        for (int o = 16; o; o >>= 1) p += __shfl_xor_sync(0xffffffffu, p, o);
        if (lane == d) qwe_own = p;
    }

    float m = -INFINITY, den = 0.f;
    float4 acc0 = make_float4(0, 0, 0, 0), acc1 = make_float4(0, 0, 0, 0);
    float pea_own = 0.f;
    int beg = g_offs[w], end = g_offs[w + 1];
    for (int t = beg; t < end; t++) {
        int src = g_ssrc[t];
        int eid = g_seid[t];
        const uint2* khr = reinterpret_cast<const uint2*>(g_kh + (size_t)src * 256);
        const float4* vr = reinterpret_cast<const float4*>(g_v + (size_t)src * 256);
        uint2 ka = khr[lane];        // halves [lane*4 .. +3]
        uint2 kb = khr[32 + lane];   // halves [128+lane*4 .. +3]
        float4 v0 = vr[lane], v1 = vr[32 + lane];
        float e_own = (lane < 8) ? __ldg(edge_attr + (size_t)eid * 8 + lane) : 0.f;

        float2 ka01 = __half22float2(*reinterpret_cast<__half2*>(&ka.x));
        float2 ka23 = __half22float2(*reinterpret_cast<__half2*>(&ka.y));
        float2 kb01 = __half22float2(*reinterpret_cast<__half2*>(&kb.x));
        float2 kb23 = __half22float2(*reinterpret_cast<__half2*>(&kb.y));

        float partial = q0.x * ka01.x + q0.y * ka01.y + q0.z * ka23.x + q0.w * ka23.y +
                        q1.x * kb01.x + q1.y * kb01.y + q1.z * kb23.x + q1.w * kb23.y +
                        qwe_own * e_own;
#pragma unroll
        for (int o = 16; o; o >>= 1) partial += __shfl_xor_sync(0xffffffffu, partial, o);
        float alpha = partial * 0.0625f;
        float mn = fmaxf(m, alpha);
        float corr = __expf(m - mn);
        float p = __expf(alpha - mn);
        m = mn;
        den = den * corr + p;
        acc0.x = acc0.x * corr + p * v0.x; acc0.y = acc0.y * corr + p * v0.y;
        acc0.z = acc0.z * corr + p * v0.z; acc0.w = acc0.w * corr + p * v0.w;
        acc1.x = acc1.x * corr + p * v1.x; acc1.y = acc1.y * corr + p * v1.y;
        acc1.z = acc1.z * corr + p * v1.z; acc1.w = acc1.w * corr + p * v1.w;
        pea_own = pea_own * corr + p * e_own;
    }
    float inv = 1.f / (den + 1e-16f);
    float pe[8];
#pragma unroll
    for (int d = 0; d < 8; d++) pe[d] = __shfl_sync(0xffffffffu, pea_own, d);
    float4 ex0 = make_float4(0, 0, 0, 0), ex1 = make_float4(0, 0, 0, 0);
#pragma unroll
    for (int d = 0; d < 8; d++) {
        float4 w0 = sWe4[d * 64 + lane], w1 = sWe4[d * 64 + 32 + lane];
        ex0.x += pe[d] * w0.x; ex0.y += pe[d] * w0.y; ex0.z += pe[d] * w0.z; ex0.w += pe[d] * w0.w;
        ex1.x += pe[d] * w1.x; ex1.y += pe[d] * w1.y; ex1.z += pe[d] * w1.z; ex1.w += pe[d] * w1.w;
    }
    float4 sk0 = *reinterpret_cast<const float4*>(g_sk + (size_t)w * 256 + lane * 4);
    float4 sk1 = *reinterpret_cast<const float4*>(g_sk + (size_t)w * 256 + 128 + lane * 4);
    float4 o0, o1;
    o0.x = fmaxf((acc0.x + ex0.x) * inv + sk0.x, 0.f);
    o0.y = fmaxf((acc0.y + ex0.y) * inv + sk0.y, 0.f);
    o0.z = fmaxf((acc0.z + ex0.z) * inv + sk0.z, 0.f);
    o0.w = fmaxf((acc0.w + ex0.w) * inv + sk0.w, 0.f);
    o1.x = fmaxf((acc1.x + ex1.x) * inv + sk1.x, 0.f);
    o1.y = fmaxf((acc1.y + ex1.y) * inv + sk1.y, 0.f);
    o1.z = fmaxf((acc1.z + ex1.z) * inv + sk1.z, 0.f);
    o1.w = fmaxf((acc1.w + ex1.w) * inv + sk1.w, 0.f);
    *reinterpret_cast<float4*>(hout + (size_t)w * 256 + lane * 4) = o0;
    *reinterpret_cast<float4*>(hout + (size_t)w * 256 + 128 + lane * 4) = o1;
    uint2 hi, lo;
    split4(o0, &hi, &lo);
    *reinterpret_cast<uint2*>(g_hb + (size_t)w * KTOT + lane * 4) = hi;
    *reinterpret_cast<uint2*>(g_hb + (size_t)w * KTOT + 256 + lane * 4) = lo;
    split4(o1, &hi, &lo);
    *reinterpret_cast<uint2*>(g_hb + (size_t)w * KTOT + 128 + lane * 4) = hi;
    *reinterpret_cast<uint2*>(g_hb + (size_t)w * KTOT + 256 + 128 + lane * 4) = lo;
}

// ---------------- decoder ----------------
__global__ void dec_kernel(const float* __restrict__ Wd, const float* __restrict__ bd,
                           float* __restrict__ out) {
    __shared__ float sW[18 * 256];
    __shared__ float sb[18];
    for (int i = threadIdx.x; i < 18 * 256; i += blockDim.x) {
        int j = i / 18, o = i % 18;
        sW[o * 256 + j] = Wd[i];
    }
    if (threadIdx.x < 18) sb[threadIdx.x] = bd[threadIdx.x];
    __syncthreads();
    int w = (blockIdx.x * blockDim.x + threadIdx.x) >> 5;
    int lane = threadIdx.x & 31;
    if (w >= N_NODES) return;
    const float* h = g_h[1];
    float hr[8];
#pragma unroll
    for (int i = 0; i < 8; i++) hr[i] = h[(size_t)w * 256 + lane + 32 * i];
    for (int o = 0; o < 18; o++) {
        float p = 0.f;
#pragma unroll
        for (int i = 0; i < 8; i++) p += hr[i] * sW[o * 256 + lane + 32 * i];
#pragma unroll
        for (int off = 16; off; off >>= 1) p += __shfl_xor_sync(0xffffffffu, p, off);
        if (lane == 0) out[w * 18 + o] = p + sb[o];
    }
}

// ---------------- launch ----------------
extern "C" void kernel_launch(void* const* d_in, const int* in_sizes, int n_in,
                              void* d_out, int out_size) {
    const float* x = (const float*)d_in[0];
    const int* ei = (const int*)d_in[1];
    const float* edge_attr = (const float*)d_in[2];
    const float* t = (const float*)d_in[3];
    const float* s = (const float*)d_in[4];
    const float* W_emb = (const float*)d_in[5];
    const float* b_emb = (const float*)d_in[6];
    const float* W_t = (const float*)d_in[7];
    const float* b_t = (const float*)d_in[8];
    const float* W_s = (const float*)d_in[9];
    const float* b_s = (const float*)d_in[10];
    const float* W_f = (const float*)d_in[11];
    const float* b_f = (const float*)d_in[12];
    const float* ln_g = (const float*)d_in[13];
    const float* ln_b = (const float*)d_in[14];
    const float* Wq = (const float*)d_in[15];
    const float* bq = (const float*)d_in[16];
    const float* Wk = (const float*)d_in[17];
    const float* bk = (const float*)d_in[18];
    const float* Wv = (const float*)d_in[19];
    const float* bv = (const float*)d_in[20];
    const float* We = (const float*)d_in[21];
    const float* be = (const float*)d_in[22];
    const float* Wskip = (const float*)d_in[23];
    const float* bskip = (const float*)d_in[24];
    const float* W_dec = (const float*)d_in[25];
    const float* b_dec = (const float*)d_in[26];
    float* out = (float*)d_out;
    (void)in_sizes; (void)n_in; (void)out_size;

    wconv_kernel<<<dim3(8, 8, 20), 256>>>(Wq, Wk, Wv, Wskip);                        // 0
    fuse_kernel<<<52, 256>>>(W_emb, W_t, W_s, W_f, b_emb, b_t, b_s, b_f, bskip, be); // 1
    encoder_kernel<<<296, 256>>>(x, t, s, ln_g, ln_b);                               // 2

    dim3 ggrid(157, 2, 4);
    gemm_wb<<<ggrid, 256>>>(0, bq, bk, bv);                                          // 3 <- profiled

    zero_deg_kernel<<<NBLK, 256>>>();                   // 4
    hist_kernel<<<(N_EDGES + 255) / 256, 256>>>(ei);    // 5
    scanA_kernel<<<NBLK, 256>>>();                      // 6
    scanB_kernel<<<1, 1>>>();                           // 7
    scanC_kernel<<<NBLK, 256>>>();                      // 8
    scatter_kernel<<<(N_EDGES + 255) / 256, 256>>>(ei); // 9

    int attn_blocks = (N_NODES * 32 + 255) / 256;
    attn_kernel<<<attn_blocks, 256>>>(We + 0 * 2048, edge_attr, 0);                  // 10
    for (int L = 1; L < N_LAYERS; L++) {
        int pin = L & 1;
        gemm_wb<<<ggrid, 256>>>(L, bq, bk, bv);
        attn_kernel<<<attn_blocks, 256>>>(We + L * 2048, edge_attr, pin);
    }
    dec_kernel<<<attn_blocks, 256>>>(W_dec, b_dec, out);
}

// round 15
// speedup vs baseline: 1.5038x; 1.0334x over previous
#include <cuda_runtime.h>
#include <cuda_bf16.h>
#include <cuda_fp16.h>
#include <math.h>
#include <stdint.h>
#include <mma.h>

using namespace nvcuda;

#define N_NODES 20000
#define N_EDGES 640000
#define HID 256
#define NH (N_NODES * HID)
#define N_LAYERS 5
#define KTOT 512       // stored split K (hi | lo)
#define GKCH 32        // GEMM K elements per pipelined chunk
#define GNCH 24        // 3 segments x 8 chunks: (hi,hi) (lo,hi) (hi,lo)
#define GLDA 40        // gemm smem leading dim (bf16; 80B, 16B-multiple)
#define NSTAGE 4
#define STAGE_ELEMS (2 * 128 * GLDA)            // A+B per stage (bf16 elems)
#define GEMM_DYN_BYTES (NSTAGE * STAGE_ELEMS * 2)  // 81920
#define LDS_STAGE 68   // epilogue staging ld (floats; 272B, 16B-multiple)
#define NBLK 79        // ceil(20000/256)

// ---------------- scratch ----------------
__device__ float g_h[2][NH];
__device__ float g_q[NH], g_k[NH], g_v[NH], g_sk[NH];
__device__ __align__(16) __half g_kh[NH];                                // K in fp16 for attention gather
__device__ __align__(256) __nv_bfloat16 g_hb[N_NODES * KTOT];            // A split [M, hi|lo]
__device__ __align__(256) __nv_bfloat16 g_Wb[4 * N_LAYERS * 256 * KTOT]; // B split [N, hi|lo]
__device__ float g_M[46 * HID];
__device__ float g_bias[HID];
__device__ float g_skbias[N_LAYERS * HID];
__device__ int g_deg[N_NODES];
__device__ int g_offs[N_NODES + 1];
__device__ int g_bsum[NBLK];
__device__ int g_cursor[N_NODES];
__device__ int g_ssrc[N_EDGES];
__device__ int g_seid[N_EDGES];

__device__ __forceinline__ void split_store(float v, __nv_bfloat16* hi_p, __nv_bfloat16* lo_p) {
    __nv_bfloat16 h = __float2bfloat16(v);
    *hi_p = h;
    *lo_p = __float2bfloat16(v - __bfloat162float(h));
}
__device__ __forceinline__ float dot4(float4 a, float4 b) {
    return a.x * b.x + a.y * b.y + a.z * b.z + a.w * b.w;
}
__device__ __forceinline__ void split4(float4 v, uint2* hi, uint2* lo) {
    __nv_bfloat16 hx = __float2bfloat16(v.x), hy = __float2bfloat16(v.y);
    __nv_bfloat16 hz = __float2bfloat16(v.z), hw = __float2bfloat16(v.w);
    __nv_bfloat162 h01 = __nv_bfloat162(hx, hy), h23 = __nv_bfloat162(hz, hw);
    hi->x = *reinterpret_cast<uint32_t*>(&h01);
    hi->y = *reinterpret_cast<uint32_t*>(&h23);
    __nv_bfloat162 l01 = __nv_bfloat162(__float2bfloat16(v.x - __bfloat162float(hx)),
                                        __float2bfloat16(v.y - __bfloat162float(hy)));
    __nv_bfloat162 l23 = __nv_bfloat162(__float2bfloat16(v.z - __bfloat162float(hz)),
                                        __float2bfloat16(v.w - __bfloat162float(hw)));
    lo->x = *reinterpret_cast<uint32_t*>(&l01);
    lo->y = *reinterpret_cast<uint32_t*>(&l23);
}
__device__ __forceinline__ void cp16(void* dst_smem, const void* src) {
    uint32_t d = (uint32_t)__cvta_generic_to_shared(dst_smem);
    asm volatile("cp.async.cg.shared.global [%0], [%1], 16;" :: "r"(d), "l"(src));
}
#define CP_COMMIT() asm volatile("cp.async.commit_group;" ::: "memory")
#define CP_WAIT2() asm volatile("cp.async.wait_group 2;" ::: "memory")
#define CP_WAIT1() asm volatile("cp.async.wait_group 1;" ::: "memory")
#define CP_WAIT0() asm volatile("cp.async.wait_group 0;" ::: "memory")

// ---------------- weight conversion: W[K,N] fp32 -> Wb[N, 512] bf16 (hi|lo) ----------------
__global__ void wconv_kernel(const float* __restrict__ Wq, const float* __restrict__ Wk,
                             const float* __restrict__ Wv, const float* __restrict__ Wsk) {
    __shared__ float s[32][33];
    int z = blockIdx.z;
    int w = z / N_LAYERS, l = z % N_LAYERS;
    const float* src = (w == 0) ? Wq : (w == 1) ? Wk : (w == 2) ? Wv : Wsk;
    src += l * 65536;
    __nv_bfloat16* dst = g_Wb + (size_t)z * 256 * KTOT;
    int k0 = blockIdx.x * 32, n0 = blockIdx.y * 32;
    int tx = threadIdx.x & 31, ty = threadIdx.x >> 5;
#pragma unroll
    for (int it = 0; it < 4; it++) {
        int r = ty + it * 8;
        s[r][tx] = src[(k0 + r) * 256 + n0 + tx];
    }
    __syncthreads();
#pragma unroll
    for (int it = 0; it < 4; it++) {
        int r = ty + it * 8;
        float v = s[tx][r];
        split_store(v, dst + (size_t)(n0 + r) * KTOT + k0 + tx,
                    dst + (size_t)(n0 + r) * KTOT + 256 + k0 + tx);
    }
}

// ---------------- fused encoder weights + skip-bias fold ----------------
__global__ void fuse_kernel(const float* __restrict__ W_emb, const float* __restrict__ W_t,
                            const float* __restrict__ W_s, const float* __restrict__ W_f,
                            const float* __restrict__ b_emb, const float* __restrict__ b_t,
                            const float* __restrict__ b_s, const float* __restrict__ b_f,
                            const float* __restrict__ bskip, const float* __restrict__ be) {
    int c = threadIdx.x;
    int r = blockIdx.x;
    if (r < 36) {
        float a = 0.f;
        for (int k = 0; k < 256; k++) a += W_emb[r * 256 + k] * W_f[k * 256 + c];
        g_M[r * 256 + c] = a;
    } else if (r < 40) {
        int rr = r - 36;
        float a = 0.f;
        for (int k = 0; k < 256; k++) a += W_t[rr * 256 + k] * W_f[(256 + k) * 256 + c];
        g_M[r * 256 + c] = a;
    } else if (r < 46) {
        int rr = r - 40;
        float a = 0.f;
        for (int k = 0; k < 256; k++) a += W_s[rr * 256 + k] * W_f[(512 + k) * 256 + c];
        g_M[r * 256 + c] = a;
    } else if (r == 46) {
        float a = b_f[c];
        for (int k = 0; k < 256; k++) {
            a += b_emb[k] * W_f[k * 256 + c];
            a += b_t[k] * W_f[(256 + k) * 256 + c];
            a += b_s[k] * W_f[(512 + k) * 256 + c];
        }
        g_bias[c] = a;
    } else {
        int l = r - 47;
        g_skbias[l * 256 + c] = bskip[l * 256 + c] + be[l * 256 + c];
    }
}

// ---------------- encoder ----------------
__global__ void encoder_kernel(const float* __restrict__ x, const float* __restrict__ t,
                               const float* __restrict__ s, const float* __restrict__ ln_g,
                               const float* __restrict__ ln_b) {
    __shared__ float sM[46 * 256];
    __shared__ float sb[256];
    __shared__ float sin_v[46];
    __shared__ float red[16];
    int tid = threadIdx.x;
    for (int i = tid; i < 46 * 256; i += 256) sM[i] = g_M[i];
    sb[tid] = g_bias[tid];
    float lg = ln_g[tid], lb = ln_b[tid];
    __syncthreads();
    for (int node = blockIdx.x; node < N_NODES; node += gridDim.x) {
        if (tid < 36) sin_v[tid] = x[node * 36 + tid];
        else if (tid < 40) sin_v[tid] = t[node * 4 + (tid - 36)];
        else if (tid < 46) sin_v[tid] = s[node * 6 + (tid - 40)];
        __syncthreads();
        float acc = sb[tid];
#pragma unroll
        for (int r = 0; r < 46; r++) acc += sin_v[r] * sM[r * 256 + tid];
        float ssum = acc, ssq = acc * acc;
#pragma unroll
        for (int o = 16; o; o >>= 1) {
            ssum += __shfl_xor_sync(0xffffffffu, ssum, o);
            ssq += __shfl_xor_sync(0xffffffffu, ssq, o);
        }
        if ((tid & 31) == 0) { red[tid >> 5] = ssum; red[8 + (tid >> 5)] = ssq; }
        __syncthreads();
        if (tid < 32) {
            float a = (tid < 8) ? red[tid] : 0.f;
            float b = (tid < 8) ? red[8 + tid] : 0.f;
#pragma unroll
            for (int o = 4; o; o >>= 1) {
                a += __shfl_xor_sync(0xffffffffu, a, o);
                b += __shfl_xor_sync(0xffffffffu, b, o);
            }
            if (tid == 0) { red[0] = a; red[1] = b; }
        }
        __syncthreads();
        float mu = red[0] * (1.f / 256.f);
        float var = red[1] * (1.f / 256.f) - mu * mu;
        float val = fmaxf((acc - mu) * rsqrtf(var + 1e-5f) * lg + lb, 0.f);
        g_h[0][node * 256 + tid] = val;
        split_store(val, g_hb + (size_t)node * KTOT + tid, g_hb + (size_t)node * KTOT + 256 + tid);
        __syncthreads();
    }
}

// ---------------- CSR build (3-phase scan) ----------------
__global__ void zero_deg_kernel() {
    int i = blockIdx.x * blockDim.x + threadIdx.x;
    if (i < N_NODES) g_deg[i] = 0;
}
__global__ void hist_kernel(const int* __restrict__ ei) {
    int e = blockIdx.x * blockDim.x + threadIdx.x;
    if (e < N_EDGES) atomicAdd(&g_deg[ei[N_EDGES + e]], 1);
}
__global__ void scanA_kernel() {
    __shared__ int wsum[8];
    int b = blockIdx.x, tid = threadIdx.x;
    int i = b * 256 + tid;
    int lane = tid & 31, wid = tid >> 5;
    int v = (i < N_NODES) ? g_deg[i] : 0;
    int x = v;
#pragma unroll
    for (int o = 1; o < 32; o <<= 1) {
        int y = __shfl_up_sync(0xffffffffu, x, o);
        if (lane >= o) x += y;
    }
    if (lane == 31) wsum[wid] = x;
    __syncthreads();
    if (wid == 0) {
        int s = (lane < 8) ? wsum[lane] : 0;
#pragma unroll
        for (int o = 1; o < 8; o <<= 1) {
            int y = __shfl_up_sync(0xffffffffu, s, o);
            if (lane >= o) s += y;
        }
        if (lane < 8) wsum[lane] = s;
    }
    __syncthreads();
    int base = (wid > 0) ? wsum[wid - 1] : 0;
    int incl = base + x;
    if (i < N_NODES) g_offs[i] = incl - v;
    if (tid == 255) g_bsum[b] = incl;
}
__global__ void scanB_kernel() {
    int total = 0;
    for (int b = 0; b < NBLK; b++) {
        int t = g_bsum[b];
        g_bsum[b] = total;
        total += t;
    }
    g_offs[N_NODES] = total;
}
__global__ void scanC_kernel() {
    int i = blockIdx.x * 256 + threadIdx.x;
    if (i < N_NODES) {
        int o = g_offs[i] + g_bsum[blockIdx.x];
        g_offs[i] = o;
        g_cursor[i] = o;
    }
}
__global__ void scatter_kernel(const int* __restrict__ ei) {
    int e = blockIdx.x * blockDim.x + threadIdx.x;
    if (e < N_EDGES) {
        int d = ei[N_EDGES + e];
        int pos = atomicAdd(&g_cursor[d], 1);
        g_ssrc[pos] = ei[e];
        g_seid[pos] = e;
    }
}

// ---------------- bf16 wmma GEMM, 128x128 tile, 4-stage cp.async pipeline ----------------
// One __syncthreads per chunk: issue(c+3) targets buf (c+3)&3 == (c-1)&3, whose compute
// finished before this iteration's barrier. w==1 also emits fp16 K copy.
__global__ void __launch_bounds__(256)
gemm_wb(int layer, const float* __restrict__ bq_, const float* __restrict__ bk_,
        const float* __restrict__ bv_) {
    extern __shared__ __align__(16) __nv_bfloat16 dyn[];  // NSTAGE * (A|B) stages
    __shared__ float sbias[128];

    int tid = threadIdx.x;
    int wid = tid >> 5, lane = tid & 31;
    int wr = wid >> 1, wc = wid & 1;
    int w = blockIdx.z;
    int row0 = blockIdx.x * 128;
    int colblk = blockIdx.y * 128;
    int col0 = colblk + wc * 64;

    const __nv_bfloat16* Bsrc = g_Wb + ((size_t)w * N_LAYERS + layer) * 256 * KTOT;
    float* C;
    const float* bias;
    if (w == 0) { C = g_q; bias = bq_ + layer * 256; }
    else if (w == 1) { C = g_k; bias = bk_ + layer * 256; }
    else if (w == 2) { C = g_v; bias = bv_ + layer * 256; }
    else { C = g_sk; bias = g_skbias + layer * 256; }

    if (tid < 128) sbias[tid] = bias[colblk + tid];

    int l0 = tid, l1 = tid + 256;
    int ar0 = l0 >> 2, ak0 = (l0 & 3) * 8;
    int ar1 = l1 >> 2, ak1 = (l1 & 3) * 8;
    int gr0 = row0 + ar0; if (gr0 >= N_NODES) gr0 = N_NODES - 1;
    int gr1 = row0 + ar1; if (gr1 >= N_NODES) gr1 = N_NODES - 1;

    wmma::fragment<wmma::accumulator, 16, 16, 16, float> acc[2][4];
#pragma unroll
    for (int m = 0; m < 2; m++)
#pragma unroll
        for (int n = 0; n < 4; n++) wmma::fill_fragment(acc[m][n], 0.f);

    auto issue = [&](int c) {
        int seg = c >> 3, cc = c & 7;
        int aoff = (seg == 1) ? 256 : 0;
        int boff = (seg == 2) ? 256 : 0;
        __nv_bfloat16* As = dyn + (c & 3) * STAGE_ELEMS;
        __nv_bfloat16* Bs = As + 128 * GLDA;
        cp16(As + ar0 * GLDA + ak0, g_hb + (size_t)gr0 * KTOT + aoff + cc * GKCH + ak0);
        cp16(As + ar1 * GLDA + ak1, g_hb + (size_t)gr1 * KTOT + aoff + cc * GKCH + ak1);
        cp16(Bs + ar0 * GLDA + ak0, Bsrc + (size_t)(colblk + ar0) * KTOT + boff + cc * GKCH + ak0);
        cp16(Bs + ar1 * GLDA + ak1, Bsrc + (size_t)(colblk + ar1) * KTOT + boff + cc * GKCH + ak1);
        CP_COMMIT();
    };

    issue(0); issue(1); issue(2);
    for (int c = 0; c < GNCH; c++) {
        int rem = GNCH - 1 - c;  // groups committed after c
        if (rem >= 2) CP_WAIT2();
        else if (rem == 1) CP_WAIT1();
        else CP_WAIT0();
        __syncthreads();
        __nv_bfloat16* As = dyn + (c & 3) * STAGE_ELEMS;
        __nv_bfloat16* Bs = As + 128 * GLDA;
#pragma unroll
        for (int ks = 0; ks < 2; ks++) {
            wmma::fragment<wmma::matrix_a, 16, 16, 16, __nv_bfloat16, wmma::row_major> af[2];
            wmma::fragment<wmma::matrix_b, 16, 16, 16, __nv_bfloat16, wmma::col_major> bf[4];
#pragma unroll
            for (int m = 0; m < 2; m++)
                wmma::load_matrix_sync(af[m], As + (wr * 32 + m * 16) * GLDA + ks * 16, GLDA);
#pragma unroll
            for (int n = 0; n < 4; n++)
                wmma::load_matrix_sync(bf[n], Bs + (wc * 64 + n * 16) * GLDA + ks * 16, GLDA);
#pragma unroll
            for (int m = 0; m < 2; m++)
#pragma unroll
                for (int n = 0; n < 4; n++) wmma::mma_sync(acc[m][n], af[m], bf[n], acc[m][n]);
        }
        if (c + 3 < GNCH) issue(c + 3);
    }
    __syncthreads();

    // epilogue: per-warp 16x64 staging (stages 0-1 region; last compute used stage 3)
    float* stage = reinterpret_cast<float*>(dyn) + wid * 16 * LDS_STAGE;
#pragma unroll
    for (int m = 0; m < 2; m++) {
        __syncwarp();
#pragma unroll
        for (int n = 0; n < 4; n++)
            wmma::store_matrix_sync(stage + n * 16, acc[m][n], LDS_STAGE, wmma::mem_row_major);
        __syncwarp();
        int rbase = row0 + wr * 32 + m * 16;
#pragma unroll
        for (int i = lane; i < 16 * 64; i += 32) {
            int r = i >> 6, cc2 = i & 63;
            int gr = rbase + r;
            if (gr < N_NODES) {
                float val = stage[r * LDS_STAGE + cc2] + sbias[wc * 64 + cc2];
                size_t idx = (size_t)gr * 256 + col0 + cc2;
                C[idx] = val;
                if (w == 1) g_kh[idx] = __float2half(val);
            }
        }
        __syncwarp();
    }
}

// ---------------- attention: lane-owned edge features, fp16 K gather, occ 4 ----------------
__global__ void __launch_bounds__(256, 4)
attn_kernel(const float* __restrict__ We_l, const float* __restrict__ edge_attr, int pin) {
    __shared__ float sWe[8 * 256];
    for (int i = threadIdx.x; i < 2048; i += blockDim.x) sWe[i] = We_l[i];
    __syncthreads();
    const float4* sWe4 = reinterpret_cast<const float4*>(sWe);
    int w = (blockIdx.x * blockDim.x + threadIdx.x) >> 5;
    int lane = threadIdx.x & 31;
    if (w >= N_NODES) return;
    float* hout = g_h[pin ^ 1];

    float4 q0 = *reinterpret_cast<const float4*>(g_q + (size_t)w * 256 + lane * 4);
    float4 q1 = *reinterpret_cast<const float4*>(g_q + (size_t)w * 256 + 128 + lane * 4);

    float qwe_own = 0.f;
#pragma unroll
    for (int d = 0; d < 8; d++) {
        float p = dot4(q0, sWe4[d * 64 + lane]) + dot4(q1, sWe4[d * 64 + 32 + lane]);
#pragma unroll
        for (int o = 16; o; o >>= 1) p += __shfl_xor_sync(0xffffffffu, p, o);
        if (lane == d) qwe_own = p;
    }

    float m = -INFINITY, den = 0.f;
    float4 acc0 = make_float4(0, 0, 0, 0), acc1 = make_float4(0, 0, 0, 0);
    float pea_own = 0.f;
    int beg = g_offs[w], end = g_offs[w + 1];
    for (int t = beg; t < end; t++) {
        int src = g_ssrc[t];
        int eid = g_seid[t];
        const uint2* khr = reinterpret_cast<const uint2*>(g_kh + (size_t)src * 256);
        const float4* vr = reinterpret_cast<const float4*>(g_v + (size_t)src * 256);
        uint2 ka = khr[lane];
        uint2 kb = khr[32 + lane];
        float4 v0 = vr[lane], v1 = vr[32 + lane];
        float e_own = (lane < 8) ? __ldg(edge_attr + (size_t)eid * 8 + lane) : 0.f;

        float2 ka01 = __half22float2(*reinterpret_cast<__half2*>(&ka.x));
        float2 ka23 = __half22float2(*reinterpret_cast<__half2*>(&ka.y));
        float2 kb01 = __half22float2(*reinterpret_cast<__half2*>(&kb.x));
        float2 kb23 = __half22float2(*reinterpret_cast<__half2*>(&kb.y));

        float partial = q0.x * ka01.x + q0.y * ka01.y + q0.z * ka23.x + q0.w * ka23.y +
                        q1.x * kb01.x + q1.y * kb01.y + q1.z * kb23.x + q1.w * kb23.y +
                        qwe_own * e_own;
#pragma unroll
        for (int o = 16; o; o >>= 1) partial += __shfl_xor_sync(0xffffffffu, partial, o);
        float alpha = partial * 0.0625f;
        float mn = fmaxf(m, alpha);
        float corr = __expf(m - mn);
        float p = __expf(alpha - mn);
        m = mn;
        den = den * corr + p;
        acc0.x = acc0.x * corr + p * v0.x; acc0.y = acc0.y * corr + p * v0.y;
        acc0.z = acc0.z * corr + p * v0.z; acc0.w = acc0.w * corr + p * v0.w;
        acc1.x = acc1.x * corr + p * v1.x; acc1.y = acc1.y * corr + p * v1.y;
        acc1.z = acc1.z * corr + p * v1.z; acc1.w = acc1.w * corr + p * v1.w;
        pea_own = pea_own * corr + p * e_own;
    }
    float inv = 1.f / (den + 1e-16f);
    float pe[8];
#pragma unroll
    for (int d = 0; d < 8; d++) pe[d] = __shfl_sync(0xffffffffu, pea_own, d);
    float4 ex0 = make_float4(0, 0, 0, 0), ex1 = make_float4(0, 0, 0, 0);
#pragma unroll
    for (int d = 0; d < 8; d++) {
        float4 w0 = sWe4[d * 64 + lane], w1 = sWe4[d * 64 + 32 + lane];
        ex0.x += pe[d] * w0.x; ex0.y += pe[d] * w0.y; ex0.z += pe[d] * w0.z; ex0.w += pe[d] * w0.w;
        ex1.x += pe[d] * w1.x; ex1.y += pe[d] * w1.y; ex1.z += pe[d] * w1.z; ex1.w += pe[d] * w1.w;
    }
    float4 sk0 = *reinterpret_cast<const float4*>(g_sk + (size_t)w * 256 + lane * 4);
    float4 sk1 = *reinterpret_cast<const float4*>(g_sk + (size_t)w * 256 + 128 + lane * 4);
    float4 o0, o1;
    o0.x = fmaxf((acc0.x + ex0.x) * inv + sk0.x, 0.f);
    o0.y = fmaxf((acc0.y + ex0.y) * inv + sk0.y, 0.f);
    o0.z = fmaxf((acc0.z + ex0.z) * inv + sk0.z, 0.f);
    o0.w = fmaxf((acc0.w + ex0.w) * inv + sk0.w, 0.f);
    o1.x = fmaxf((acc1.x + ex1.x) * inv + sk1.x, 0.f);
    o1.y = fmaxf((acc1.y + ex1.y) * inv + sk1.y, 0.f);
    o1.z = fmaxf((acc1.z + ex1.z) * inv + sk1.z, 0.f);
    o1.w = fmaxf((acc1.w + ex1.w) * inv + sk1.w, 0.f);
    *reinterpret_cast<float4*>(hout + (size_t)w * 256 + lane * 4) = o0;
    *reinterpret_cast<float4*>(hout + (size_t)w * 256 + 128 + lane * 4) = o1;
    uint2 hi, lo;
    split4(o0, &hi, &lo);
    *reinterpret_cast<uint2*>(g_hb + (size_t)w * KTOT + lane * 4) = hi;
    *reinterpret_cast<uint2*>(g_hb + (size_t)w * KTOT + 256 + lane * 4) = lo;
    split4(o1, &hi, &lo);
    *reinterpret_cast<uint2*>(g_hb + (size_t)w * KTOT + 128 + lane * 4) = hi;
    *reinterpret_cast<uint2*>(g_hb + (size_t)w * KTOT + 256 + 128 + lane * 4) = lo;
}

// ---------------- decoder ----------------
__global__ void dec_kernel(const float* __restrict__ Wd, const float* __restrict__ bd,
                           float* __restrict__ out) {
    __shared__ float sW[18 * 256];
    __shared__ float sb[18];
    for (int i = threadIdx.x; i < 18 * 256; i += blockDim.x) {
        int j = i / 18, o = i % 18;
        sW[o * 256 + j] = Wd[i];
    }
    if (threadIdx.x < 18) sb[threadIdx.x] = bd[threadIdx.x];
    __syncthreads();
    int w = (blockIdx.x * blockDim.x + threadIdx.x) >> 5;
    int lane = threadIdx.x & 31;
    if (w >= N_NODES) return;
    const float* h = g_h[1];
    float hr[8];
#pragma unroll
    for (int i = 0; i < 8; i++) hr[i] = h[(size_t)w * 256 + lane + 32 * i];
    for (int o = 0; o < 18; o++) {
        float p = 0.f;
#pragma unroll
        for (int i = 0; i < 8; i++) p += hr[i] * sW[o * 256 + lane + 32 * i];
#pragma unroll
        for (int off = 16; off; off >>= 1) p += __shfl_xor_sync(0xffffffffu, p, off);
        if (lane == 0) out[w * 18 + o] = p + sb[o];
    }
}

// ---------------- launch ----------------
extern "C" void kernel_launch(void* const* d_in, const int* in_sizes, int n_in,
                              void* d_out, int out_size) {
    const float* x = (const float*)d_in[0];
    const int* ei = (const int*)d_in[1];
    const float* edge_attr = (const float*)d_in[2];
    const float* t = (const float*)d_in[3];
    const float* s = (const float*)d_in[4];
    const float* W_emb = (const float*)d_in[5];
    const float* b_emb = (const float*)d_in[6];
    const float* W_t = (const float*)d_in[7];
    const float* b_t = (const float*)d_in[8];
    const float* W_s = (const float*)d_in[9];
    const float* b_s = (const float*)d_in[10];
    const float* W_f = (const float*)d_in[11];
    const float* b_f = (const float*)d_in[12];
    const float* ln_g = (const float*)d_in[13];
    const float* ln_b = (const float*)d_in[14];
    const float* Wq = (const float*)d_in[15];
    const float* bq = (const float*)d_in[16];
    const float* Wk = (const float*)d_in[17];
    const float* bk = (const float*)d_in[18];
    const float* Wv = (const float*)d_in[19];
    const float* bv = (const float*)d_in[20];
    const float* We = (const float*)d_in[21];
    const float* be = (const float*)d_in[22];
    const float* Wskip = (const float*)d_in[23];
    const float* bskip = (const float*)d_in[24];
    const float* W_dec = (const float*)d_in[25];
    const float* b_dec = (const float*)d_in[26];
    float* out = (float*)d_out;
    (void)in_sizes; (void)n_in; (void)out_size;

    cudaFuncSetAttribute(gemm_wb, cudaFuncAttributeMaxDynamicSharedMemorySize, GEMM_DYN_BYTES);

    wconv_kernel<<<dim3(8, 8, 20), 256>>>(Wq, Wk, Wv, Wskip);                        // 0
    fuse_kernel<<<52, 256>>>(W_emb, W_t, W_s, W_f, b_emb, b_t, b_s, b_f, bskip, be); // 1
    encoder_kernel<<<296, 256>>>(x, t, s, ln_g, ln_b);                               // 2

    dim3 ggrid(157, 2, 4);
    gemm_wb<<<ggrid, 256, GEMM_DYN_BYTES>>>(0, bq, bk, bv);                          // 3 <- profiled

    zero_deg_kernel<<<NBLK, 256>>>();                   // 4
    hist_kernel<<<(N_EDGES + 255) / 256, 256>>>(ei);    // 5
    scanA_kernel<<<NBLK, 256>>>();                      // 6
    scanB_kernel<<<1, 1>>>();                           // 7
    scanC_kernel<<<NBLK, 256>>>();                      // 8
    scatter_kernel<<<(N_EDGES + 255) / 256, 256>>>(ei); // 9

    int attn_blocks = (N_NODES * 32 + 255) / 256;
    attn_kernel<<<attn_blocks, 256>>>(We + 0 * 2048, edge_attr, 0);                  // 10
    for (int L = 1; L < N_LAYERS; L++) {
        int pin = L & 1;
        gemm_wb<<<ggrid, 256, GEMM_DYN_BYTES>>>(L, bq, bk, bv);
        attn_kernel<<<attn_blocks, 256>>>(We + L * 2048, edge_attr, pin);
    }
    dec_kernel<<<attn_blocks, 256>>>(W_dec, b_dec, out);
}

// round 16
// speedup vs baseline: 1.5191x; 1.0101x over previous
#include <cuda_runtime.h>
#include <cuda_bf16.h>
#include <cuda_fp16.h>
#include <math.h>
#include <stdint.h>
#include <mma.h>

using namespace nvcuda;

#define N_NODES 20000
#define N_EDGES 640000
#define HID 256
#define NH (N_NODES * HID)
#define N_LAYERS 5
#define KTOT 512       // stored split K (hi | lo)
#define GKCH 32        // GEMM K elements per pipelined chunk
#define GNCH 24        // 3 segments x 8 chunks: (hi,hi) (lo,hi) (hi,lo)
#define GLDA 40        // gemm smem leading dim (bf16; 80B, 16B-multiple)
#define NSTAGE 4
#define STAGE_ELEMS (2 * 128 * GLDA)               // A+B per stage (bf16 elems)
#define GEMM_DYN_BYTES (NSTAGE * STAGE_ELEMS * 2)  // 81920
#define LDS_STAGE 68   // epilogue staging ld (floats; 272B, 16B-multiple)
#define NBLK 79        // ceil(20000/256)

// ---------------- scratch ----------------
__device__ float g_h[2][NH];
__device__ float g_q[NH], g_sk[NH];
__device__ __align__(16) __half g_kh[NH];                                // K fp16 (attention gather)
__device__ __align__(16) __half g_vh[NH];                                // V fp16 (attention gather)
__device__ __align__(256) __nv_bfloat16 g_hb[N_NODES * KTOT];            // A split [M, hi|lo]
__device__ __align__(256) __nv_bfloat16 g_Wb[4 * N_LAYERS * 256 * KTOT]; // B split [N, hi|lo]
__device__ float g_M[46 * HID];
__device__ float g_bias[HID];
__device__ float g_skbias[N_LAYERS * HID];
__device__ int g_deg[N_NODES];
__device__ int g_offs[N_NODES + 1];
__device__ int g_bsum[NBLK];
__device__ int g_cursor[N_NODES];
__device__ int g_ssrc[N_EDGES];
__device__ int g_seid[N_EDGES];

__device__ __forceinline__ void split_store(float v, __nv_bfloat16* hi_p, __nv_bfloat16* lo_p) {
    __nv_bfloat16 h = __float2bfloat16(v);
    *hi_p = h;
    *lo_p = __float2bfloat16(v - __bfloat162float(h));
}
__device__ __forceinline__ float dot4(float4 a, float4 b) {
    return a.x * b.x + a.y * b.y + a.z * b.z + a.w * b.w;
}
__device__ __forceinline__ void split4(float4 v, uint2* hi, uint2* lo) {
    __nv_bfloat16 hx = __float2bfloat16(v.x), hy = __float2bfloat16(v.y);
    __nv_bfloat16 hz = __float2bfloat16(v.z), hw = __float2bfloat16(v.w);
    __nv_bfloat162 h01 = __nv_bfloat162(hx, hy), h23 = __nv_bfloat162(hz, hw);
    hi->x = *reinterpret_cast<uint32_t*>(&h01);
    hi->y = *reinterpret_cast<uint32_t*>(&h23);
    __nv_bfloat162 l01 = __nv_bfloat162(__float2bfloat16(v.x - __bfloat162float(hx)),
                                        __float2bfloat16(v.y - __bfloat162float(hy)));
    __nv_bfloat162 l23 = __nv_bfloat162(__float2bfloat16(v.z - __bfloat162float(hz)),
                                        __float2bfloat16(v.w - __bfloat162float(hw)));
    lo->x = *reinterpret_cast<uint32_t*>(&l01);
    lo->y = *reinterpret_cast<uint32_t*>(&l23);
}
__device__ __forceinline__ void cp16(void* dst_smem, const void* src) {
    uint32_t d = (uint32_t)__cvta_generic_to_shared(dst_smem);
    asm volatile("cp.async.cg.shared.global [%0], [%1], 16;" :: "r"(d), "l"(src));
}
#define CP_COMMIT() asm volatile("cp.async.commit_group;" ::: "memory")
#define CP_WAIT2() asm volatile("cp.async.wait_group 2;" ::: "memory")
#define CP_WAIT1() asm volatile("cp.async.wait_group 1;" ::: "memory")
#define CP_WAIT0() asm volatile("cp.async.wait_group 0;" ::: "memory")

// ---------------- weight conversion: W[K,N] fp32 -> Wb[N, 512] bf16 (hi|lo) ----------------
__global__ void wconv_kernel(const float* __restrict__ Wq, const float* __restrict__ Wk,
                             const float* __restrict__ Wv, const float* __restrict__ Wsk) {
    __shared__ float s[32][33];
    int z = blockIdx.z;
    int w = z / N_LAYERS, l = z % N_LAYERS;
    const float* src = (w == 0) ? Wq : (w == 1) ? Wk : (w == 2) ? Wv : Wsk;
    src += l * 65536;
    __nv_bfloat16* dst = g_Wb + (size_t)z * 256 * KTOT;
    int k0 = blockIdx.x * 32, n0 = blockIdx.y * 32;
    int tx = threadIdx.x & 31, ty = threadIdx.x >> 5;
#pragma unroll
    for (int it = 0; it < 4; it++) {
        int r = ty + it * 8;
        s[r][tx] = src[(k0 + r) * 256 + n0 + tx];
    }
    __syncthreads();
#pragma unroll
    for (int it = 0; it < 4; it++) {
        int r = ty + it * 8;
        float v = s[tx][r];
        split_store(v, dst + (size_t)(n0 + r) * KTOT + k0 + tx,
                    dst + (size_t)(n0 + r) * KTOT + 256 + k0 + tx);
    }
}

// ---------------- fused encoder weights + skip-bias fold ----------------
__global__ void fuse_kernel(const float* __restrict__ W_emb, const float* __restrict__ W_t,
                            const float* __restrict__ W_s, const float* __restrict__ W_f,
                            const float* __restrict__ b_emb, const float* __restrict__ b_t,
                            const float* __restrict__ b_s, const float* __restrict__ b_f,
                            const float* __restrict__ bskip, const float* __restrict__ be) {
    int c = threadIdx.x;
    int r = blockIdx.x;
    if (r < 36) {
        float a = 0.f;
        for (int k = 0; k < 256; k++) a += W_emb[r * 256 + k] * W_f[k * 256 + c];
        g_M[r * 256 + c] = a;
    } else if (r < 40) {
        int rr = r - 36;
        float a = 0.f;
        for (int k = 0; k < 256; k++) a += W_t[rr * 256 + k] * W_f[(256 + k) * 256 + c];
        g_M[r * 256 + c] = a;
    } else if (r < 46) {
        int rr = r - 40;
        float a = 0.f;
        for (int k = 0; k < 256; k++) a += W_s[rr * 256 + k] * W_f[(512 + k) * 256 + c];
        g_M[r * 256 + c] = a;
    } else if (r == 46) {
        float a = b_f[c];
        for (int k = 0; k < 256; k++) {
            a += b_emb[k] * W_f[k * 256 + c];
            a += b_t[k] * W_f[(256 + k) * 256 + c];
            a += b_s[k] * W_f[(512 + k) * 256 + c];
        }
        g_bias[c] = a;
    } else {
        int l = r - 47;
        g_skbias[l * 256 + c] = bskip[l * 256 + c] + be[l * 256 + c];
    }
}

// ---------------- encoder ----------------
__global__ void encoder_kernel(const float* __restrict__ x, const float* __restrict__ t,
                               const float* __restrict__ s, const float* __restrict__ ln_g,
                               const float* __restrict__ ln_b) {
    __shared__ float sM[46 * 256];
    __shared__ float sb[256];
    __shared__ float sin_v[46];
    __shared__ float red[16];
    int tid = threadIdx.x;
    for (int i = tid; i < 46 * 256; i += 256) sM[i] = g_M[i];
    sb[tid] = g_bias[tid];
    float lg = ln_g[tid], lb = ln_b[tid];
    __syncthreads();
    for (int node = blockIdx.x; node < N_NODES; node += gridDim.x) {
        if (tid < 36) sin_v[tid] = x[node * 36 + tid];
        else if (tid < 40) sin_v[tid] = t[node * 4 + (tid - 36)];
        else if (tid < 46) sin_v[tid] = s[node * 6 + (tid - 40)];
        __syncthreads();
        float acc = sb[tid];
#pragma unroll
        for (int r = 0; r < 46; r++) acc += sin_v[r] * sM[r * 256 + tid];
        float ssum = acc, ssq = acc * acc;
#pragma unroll
        for (int o = 16; o; o >>= 1) {
            ssum += __shfl_xor_sync(0xffffffffu, ssum, o);
            ssq += __shfl_xor_sync(0xffffffffu, ssq, o);
        }
        if ((tid & 31) == 0) { red[tid >> 5] = ssum; red[8 + (tid >> 5)] = ssq; }
        __syncthreads();
        if (tid < 32) {
            float a = (tid < 8) ? red[tid] : 0.f;
            float b = (tid < 8) ? red[8 + tid] : 0.f;
#pragma unroll
            for (int o = 4; o; o >>= 1) {
                a += __shfl_xor_sync(0xffffffffu, a, o);
                b += __shfl_xor_sync(0xffffffffu, b, o);
            }
            if (tid == 0) { red[0] = a; red[1] = b; }
        }
        __syncthreads();
        float mu = red[0] * (1.f / 256.f);
        float var = red[1] * (1.f / 256.f) - mu * mu;
        float val = fmaxf((acc - mu) * rsqrtf(var + 1e-5f) * lg + lb, 0.f);
        g_h[0][node * 256 + tid] = val;
        split_store(val, g_hb + (size_t)node * KTOT + tid, g_hb + (size_t)node * KTOT + 256 + tid);
        __syncthreads();
    }
}

// ---------------- CSR build (3-phase scan) ----------------
__global__ void zero_deg_kernel() {
    int i = blockIdx.x * blockDim.x + threadIdx.x;
    if (i < N_NODES) g_deg[i] = 0;
}
__global__ void hist_kernel(const int* __restrict__ ei) {
    int e = blockIdx.x * blockDim.x + threadIdx.x;
    if (e < N_EDGES) atomicAdd(&g_deg[ei[N_EDGES + e]], 1);
}
__global__ void scanA_kernel() {
    __shared__ int wsum[8];
    int b = blockIdx.x, tid = threadIdx.x;
    int i = b * 256 + tid;
    int lane = tid & 31, wid = tid >> 5;
    int v = (i < N_NODES) ? g_deg[i] : 0;
    int x = v;
#pragma unroll
    for (int o = 1; o < 32; o <<= 1) {
        int y = __shfl_up_sync(0xffffffffu, x, o);
        if (lane >= o) x += y;
    }
    if (lane == 31) wsum[wid] = x;
    __syncthreads();
    if (wid == 0) {
        int s = (lane < 8) ? wsum[lane] : 0;
#pragma unroll
        for (int o = 1; o < 8; o <<= 1) {
            int y = __shfl_up_sync(0xffffffffu, s, o);
            if (lane >= o) s += y;
        }
        if (lane < 8) wsum[lane] = s;
    }
    __syncthreads();
    int base = (wid > 0) ? wsum[wid - 1] : 0;
    int incl = base + x;
    if (i < N_NODES) g_offs[i] = incl - v;
    if (tid == 255) g_bsum[b] = incl;
}
__global__ void scanB_kernel() {
    int total = 0;
    for (int b = 0; b < NBLK; b++) {
        int t = g_bsum[b];
        g_bsum[b] = total;
        total += t;
    }
    g_offs[N_NODES] = total;
}
__global__ void scanC_kernel() {
    int i = blockIdx.x * 256 + threadIdx.x;
    if (i < N_NODES) {
        int o = g_offs[i] + g_bsum[blockIdx.x];
        g_offs[i] = o;
        g_cursor[i] = o;
    }
}
__global__ void scatter_kernel(const int* __restrict__ ei) {
    int e = blockIdx.x * blockDim.x + threadIdx.x;
    if (e < N_EDGES) {
        int d = ei[N_EDGES + e];
        int pos = atomicAdd(&g_cursor[d], 1);
        g_ssrc[pos] = ei[e];
        g_seid[pos] = e;
    }
}

// ---------------- bf16 wmma GEMM, 128x128 tile, 4-stage cp.async pipeline ----------------
// w==0 -> g_q fp32; w==3 -> g_sk fp32; w==1 -> g_kh fp16 only; w==2 -> g_vh fp16 only.
__global__ void __launch_bounds__(256)
gemm_wb(int layer, const float* __restrict__ bq_, const float* __restrict__ bk_,
        const float* __restrict__ bv_) {
    extern __shared__ __align__(16) __nv_bfloat16 dyn[];  // NSTAGE * (A|B) stages
    __shared__ float sbias[128];

    int tid = threadIdx.x;
    int wid = tid >> 5, lane = tid & 31;
    int wr = wid >> 1, wc = wid & 1;
    int w = blockIdx.z;
    int row0 = blockIdx.x * 128;
    int colblk = blockIdx.y * 128;
    int col0 = colblk + wc * 64;

    const __nv_bfloat16* Bsrc = g_Wb + ((size_t)w * N_LAYERS + layer) * 256 * KTOT;
    float* C = nullptr;
    __half* Ch = nullptr;
    const float* bias;
    if (w == 0) { C = g_q; bias = bq_ + layer * 256; }
    else if (w == 1) { Ch = g_kh; bias = bk_ + layer * 256; }
    else if (w == 2) { Ch = g_vh; bias = bv_ + layer * 256; }
    else { C = g_sk; bias = g_skbias + layer * 256; }

    if (tid < 128) sbias[tid] = bias[colblk + tid];

    int l0 = tid, l1 = tid + 256;
    int ar0 = l0 >> 2, ak0 = (l0 & 3) * 8;
    int ar1 = l1 >> 2, ak1 = (l1 & 3) * 8;
    int gr0 = row0 + ar0; if (gr0 >= N_NODES) gr0 = N_NODES - 1;
    int gr1 = row0 + ar1; if (gr1 >= N_NODES) gr1 = N_NODES - 1;

    wmma::fragment<wmma::accumulator, 16, 16, 16, float> acc[2][4];
#pragma unroll
    for (int m = 0; m < 2; m++)
#pragma unroll
        for (int n = 0; n < 4; n++) wmma::fill_fragment(acc[m][n], 0.f);

    auto issue = [&](int c) {
        int seg = c >> 3, cc = c & 7;
        int aoff = (seg == 1) ? 256 : 0;
        int boff = (seg == 2) ? 256 : 0;
        __nv_bfloat16* As = dyn + (c & 3) * STAGE_ELEMS;
        __nv_bfloat16* Bs = As + 128 * GLDA;
        cp16(As + ar0 * GLDA + ak0, g_hb + (size_t)gr0 * KTOT + aoff + cc * GKCH + ak0);
        cp16(As + ar1 * GLDA + ak1, g_hb + (size_t)gr1 * KTOT + aoff + cc * GKCH + ak1);
        cp16(Bs + ar0 * GLDA + ak0, Bsrc + (size_t)(colblk + ar0) * KTOT + boff + cc * GKCH + ak0);
        cp16(Bs + ar1 * GLDA + ak1, Bsrc + (size_t)(colblk + ar1) * KTOT + boff + cc * GKCH + ak1);
        CP_COMMIT();
    };

    issue(0); issue(1); issue(2);
    for (int c = 0; c < GNCH; c++) {
        int rem = GNCH - 1 - c;
        if (rem >= 2) CP_WAIT2();
        else if (rem == 1) CP_WAIT1();
        else CP_WAIT0();
        __syncthreads();
        __nv_bfloat16* As = dyn + (c & 3) * STAGE_ELEMS;
        __nv_bfloat16* Bs = As + 128 * GLDA;
#pragma unroll
        for (int ks = 0; ks < 2; ks++) {
            wmma::fragment<wmma::matrix_a, 16, 16, 16, __nv_bfloat16, wmma::row_major> af[2];
            wmma::fragment<wmma::matrix_b, 16, 16, 16, __nv_bfloat16, wmma::col_major> bf[4];
#pragma unroll
            for (int m = 0; m < 2; m++)
                wmma::load_matrix_sync(af[m], As + (wr * 32 + m * 16) * GLDA + ks * 16, GLDA);
#pragma unroll
            for (int n = 0; n < 4; n++)
                wmma::load_matrix_sync(bf[n], Bs + (wc * 64 + n * 16) * GLDA + ks * 16, GLDA);
#pragma unroll
            for (int m = 0; m < 2; m++)
#pragma unroll
                for (int n = 0; n < 4; n++) wmma::mma_sync(acc[m][n], af[m], bf[n], acc[m][n]);
        }
        if (c + 3 < GNCH) issue(c + 3);
    }
    __syncthreads();

    float* stage = reinterpret_cast<float*>(dyn) + wid * 16 * LDS_STAGE;
#pragma unroll
    for (int m = 0; m < 2; m++) {
        __syncwarp();
#pragma unroll
        for (int n = 0; n < 4; n++)
            wmma::store_matrix_sync(stage + n * 16, acc[m][n], LDS_STAGE, wmma::mem_row_major);
        __syncwarp();
        int rbase = row0 + wr * 32 + m * 16;
#pragma unroll
        for (int i = lane; i < 16 * 64; i += 32) {
            int r = i >> 6, cc2 = i & 63;
            int gr = rbase + r;
            if (gr < N_NODES) {
                float val = stage[r * LDS_STAGE + cc2] + sbias[wc * 64 + cc2];
                size_t idx = (size_t)gr * 256 + col0 + cc2;
                if (C) C[idx] = val;
                else Ch[idx] = __float2half(val);
            }
        }
        __syncwarp();
    }
}

// ---------------- attention: lane-owned edge features, fp16 K+V gather, occ 4 ----------------
__global__ void __launch_bounds__(256, 4)
attn_kernel(const float* __restrict__ We_l, const float* __restrict__ edge_attr, int pin) {
    __shared__ float sWe[8 * 256];
    for (int i = threadIdx.x; i < 2048; i += blockDim.x) sWe[i] = We_l[i];
    __syncthreads();
    const float4* sWe4 = reinterpret_cast<const float4*>(sWe);
    int w = (blockIdx.x * blockDim.x + threadIdx.x) >> 5;
    int lane = threadIdx.x & 31;
    if (w >= N_NODES) return;
    float* hout = g_h[pin ^ 1];

    float4 q0 = *reinterpret_cast<const float4*>(g_q + (size_t)w * 256 + lane * 4);
    float4 q1 = *reinterpret_cast<const float4*>(g_q + (size_t)w * 256 + 128 + lane * 4);

    float qwe_own = 0.f;
#pragma unroll
    for (int d = 0; d < 8; d++) {
        float p = dot4(q0, sWe4[d * 64 + lane]) + dot4(q1, sWe4[d * 64 + 32 + lane]);
#pragma unroll
        for (int o = 16; o; o >>= 1) p += __shfl_xor_sync(0xffffffffu, p, o);
        if (lane == d) qwe_own = p;
    }

    float m = -INFINITY, den = 0.f;
    float4 acc0 = make_float4(0, 0, 0, 0), acc1 = make_float4(0, 0, 0, 0);
    float pea_own = 0.f;
    int beg = g_offs[w], end = g_offs[w + 1];
    for (int t = beg; t < end; t++) {
        int src = g_ssrc[t];
        int eid = g_seid[t];
        const uint2* khr = reinterpret_cast<const uint2*>(g_kh + (size_t)src * 256);
        const uint2* vhr = reinterpret_cast<const uint2*>(g_vh + (size_t)src * 256);
        uint2 ka = khr[lane];
        uint2 kb = khr[32 + lane];
        uint2 va = vhr[lane];
        uint2 vb = vhr[32 + lane];
        float e_own = (lane < 8) ? __ldg(edge_attr + (size_t)eid * 8 + lane) : 0.f;

        float2 ka01 = __half22float2(*reinterpret_cast<__half2*>(&ka.x));
        float2 ka23 = __half22float2(*reinterpret_cast<__half2*>(&ka.y));
        float2 kb01 = __half22float2(*reinterpret_cast<__half2*>(&kb.x));
        float2 kb23 = __half22float2(*reinterpret_cast<__half2*>(&kb.y));
        float2 va01 = __half22float2(*reinterpret_cast<__half2*>(&va.x));
        float2 va23 = __half22float2(*reinterpret_cast<__half2*>(&va.y));
        float2 vb01 = __half22float2(*reinterpret_cast<__half2*>(&vb.x));
        float2 vb23 = __half22float2(*reinterpret_cast<__half2*>(&vb.y));

        float partial = q0.x * ka01.x + q0.y * ka01.y + q0.z * ka23.x + q0.w * ka23.y +
                        q1.x * kb01.x + q1.y * kb01.y + q1.z * kb23.x + q1.w * kb23.y +
                        qwe_own * e_own;
#pragma unroll
        for (int o = 16; o; o >>= 1) partial += __shfl_xor_sync(0xffffffffu, partial, o);
        float alpha = partial * 0.0625f;
        float mn = fmaxf(m, alpha);
        float corr = __expf(m - mn);
        float p = __expf(alpha - mn);
        m = mn;
        den = den * corr + p;
        acc0.x = acc0.x * corr + p * va01.x; acc0.y = acc0.y * corr + p * va01.y;
        acc0.z = acc0.z * corr + p * va23.x; acc0.w = acc0.w * corr + p * va23.y;
        acc1.x = acc1.x * corr + p * vb01.x; acc1.y = acc1.y * corr + p * vb01.y;
        acc1.z = acc1.z * corr + p * vb23.x; acc1.w = acc1.w * corr + p * vb23.y;
        pea_own = pea_own * corr + p * e_own;
    }
    float inv = 1.f / (den + 1e-16f);
    float pe[8];
#pragma unroll
    for (int d = 0; d < 8; d++) pe[d] = __shfl_sync(0xffffffffu, pea_own, d);
    float4 ex0 = make_float4(0, 0, 0, 0), ex1 = make_float4(0, 0, 0, 0);
#pragma unroll
    for (int d = 0; d < 8; d++) {
        float4 w0 = sWe4[d * 64 + lane], w1 = sWe4[d * 64 + 32 + lane];
        ex0.x += pe[d] * w0.x; ex0.y += pe[d] * w0.y; ex0.z += pe[d] * w0.z; ex0.w += pe[d] * w0.w;
        ex1.x += pe[d] * w1.x; ex1.y += pe[d] * w1.y; ex1.z += pe[d] * w1.z; ex1.w += pe[d] * w1.w;
    }
    float4 sk0 = *reinterpret_cast<const float4*>(g_sk + (size_t)w * 256 + lane * 4);
    float4 sk1 = *reinterpret_cast<const float4*>(g_sk + (size_t)w * 256 + 128 + lane * 4);
    float4 o0, o1;
    o0.x = fmaxf((acc0.x + ex0.x) * inv + sk0.x, 0.f);
    o0.y = fmaxf((acc0.y + ex0.y) * inv + sk0.y, 0.f);
    o0.z = fmaxf((acc0.z + ex0.z) * inv + sk0.z, 0.f);
    o0.w = fmaxf((acc0.w + ex0.w) * inv + sk0.w, 0.f);
    o1.x = fmaxf((acc1.x + ex1.x) * inv + sk1.x, 0.f);
    o1.y = fmaxf((acc1.y + ex1.y) * inv + sk1.y, 0.f);
    o1.z = fmaxf((acc1.z + ex1.z) * inv + sk1.z, 0.f);
    o1.w = fmaxf((acc1.w + ex1.w) * inv + sk1.w, 0.f);
    *reinterpret_cast<float4*>(hout + (size_t)w * 256 + lane * 4) = o0;
    *reinterpret_cast<float4*>(hout + (size_t)w * 256 + 128 + lane * 4) = o1;
    uint2 hi, lo;
    split4(o0, &hi, &lo);
    *reinterpret_cast<uint2*>(g_hb + (size_t)w * KTOT + lane * 4) = hi;
    *reinterpret_cast<uint2*>(g_hb + (size_t)w * KTOT + 256 + lane * 4) = lo;
    split4(o1, &hi, &lo);
    *reinterpret_cast<uint2*>(g_hb + (size_t)w * KTOT + 128 + lane * 4) = hi;
    *reinterpret_cast<uint2*>(g_hb + (size_t)w * KTOT + 256 + 128 + lane * 4) = lo;
}

// ---------------- decoder ----------------
__global__ void dec_kernel(const float* __restrict__ Wd, const float* __restrict__ bd,
                           float* __restrict__ out) {
    __shared__ float sW[18 * 256];
    __shared__ float sb[18];
    for (int i = threadIdx.x; i < 18 * 256; i += blockDim.x) {
        int j = i / 18, o = i % 18;
        sW[o * 256 + j] = Wd[i];
    }
    if (threadIdx.x < 18) sb[threadIdx.x] = bd[threadIdx.x];
    __syncthreads();
    int w = (blockIdx.x * blockDim.x + threadIdx.x) >> 5;
    int lane = threadIdx.x & 31;
    if (w >= N_NODES) return;
    const float* h = g_h[1];
    float hr[8];
#pragma unroll
    for (int i = 0; i < 8; i++) hr[i] = h[(size_t)w * 256 + lane + 32 * i];
    for (int o = 0; o < 18; o++) {
        float p = 0.f;
#pragma unroll
        for (int i = 0; i < 8; i++) p += hr[i] * sW[o * 256 + lane + 32 * i];
#pragma unroll
        for (int off = 16; off; off >>= 1) p += __shfl_xor_sync(0xffffffffu, p, off);
        if (lane == 0) out[w * 18 + o] = p + sb[o];
    }
}

// ---------------- launch ----------------
extern "C" void kernel_launch(void* const* d_in, const int* in_sizes, int n_in,
                              void* d_out, int out_size) {
    const float* x = (const float*)d_in[0];
    const int* ei = (const int*)d_in[1];
    const float* edge_attr = (const float*)d_in[2];
    const float* t = (const float*)d_in[3];
    const float* s = (const float*)d_in[4];
    const float* W_emb = (const float*)d_in[5];
    const float* b_emb = (const float*)d_in[6];
    const float* W_t = (const float*)d_in[7];
    const float* b_t = (const float*)d_in[8];
    const float* W_s = (const float*)d_in[9];
    const float* b_s = (const float*)d_in[10];
    const float* W_f = (const float*)d_in[11];
    const float* b_f = (const float*)d_in[12];
    const float* ln_g = (const float*)d_in[13];
    const float* ln_b = (const float*)d_in[14];
    const float* Wq = (const float*)d_in[15];
    const float* bq = (const float*)d_in[16];
    const float* Wk = (const float*)d_in[17];
    const float* bk = (const float*)d_in[18];
    const float* Wv = (const float*)d_in[19];
    const float* bv = (const float*)d_in[20];
    const float* We = (const float*)d_in[21];
    const float* be = (const float*)d_in[22];
    const float* Wskip = (const float*)d_in[23];
    const float* bskip = (const float*)d_in[24];
    const float* W_dec = (const float*)d_in[25];
    const float* b_dec = (const float*)d_in[26];
    float* out = (float*)d_out;
    (void)in_sizes; (void)n_in; (void)out_size;

    cudaFuncSetAttribute(gemm_wb, cudaFuncAttributeMaxDynamicSharedMemorySize, GEMM_DYN_BYTES);

    wconv_kernel<<<dim3(8, 8, 20), 256>>>(Wq, Wk, Wv, Wskip);                        // 0
    fuse_kernel<<<52, 256>>>(W_emb, W_t, W_s, W_f, b_emb, b_t, b_s, b_f, bskip, be); // 1
    encoder_kernel<<<296, 256>>>(x, t, s, ln_g, ln_b);                               // 2

    dim3 ggrid(157, 2, 4);
    gemm_wb<<<ggrid, 256, GEMM_DYN_BYTES>>>(0, bq, bk, bv);                          // 3 <- profiled

    zero_deg_kernel<<<NBLK, 256>>>();                   // 4
    hist_kernel<<<(N_EDGES + 255) / 256, 256>>>(ei);    // 5
    scanA_kernel<<<NBLK, 256>>>();                      // 6
    scanB_kernel<<<1, 1>>>();                           // 7
    scanC_kernel<<<NBLK, 256>>>();                      // 8
    scatter_kernel<<<(N_EDGES + 255) / 256, 256>>>(ei); // 9

    int attn_blocks = (N_NODES * 32 + 255) / 256;
    attn_kernel<<<attn_blocks, 256>>>(We + 0 * 2048, edge_attr, 0);                  // 10
    for (int L = 1; L < N_LAYERS; L++) {
        int pin = L & 1;
        gemm_wb<<<ggrid, 256, GEMM_DYN_BYTES>>>(L, bq, bk, bv);
        attn_kernel<<<attn_blocks, 256>>>(We + L * 2048, edge_attr, pin);
    }
    dec_kernel<<<attn_blocks, 256>>>(W_dec, b_dec, out);
}

// round 17
// speedup vs baseline: 1.5796x; 1.0398x over previous
#include <cuda_runtime.h>
#include <cuda_bf16.h>
#include <cuda_fp16.h>
#include <math.h>
#include <stdint.h>
#include <mma.h>

using namespace nvcuda;

#define N_NODES 20000
#define N_EDGES 640000
#define HID 256
#define NH (N_NODES * HID)
#define N_LAYERS 5
#define KTOT 512       // stored split K (hi | lo)
#define GKCH 32        // GEMM K elements per pipelined chunk
#define GNCH 24        // 3 segments x 8 chunks: (hi,hi) (lo,hi) (hi,lo)
#define GLDA 40        // gemm smem leading dim (bf16; 80B, 16B-multiple)
#define NSTAGE 4
#define STAGE_ELEMS (2 * 128 * GLDA)               // A+B per stage (bf16 elems)
#define GEMM_DYN_BYTES (NSTAGE * STAGE_ELEMS * 2)  // 81920
#define LDS_STAGE 68   // epilogue staging ld (floats; 272B, 16B-multiple)
#define NBLK 79        // ceil(20000/256)

// ---------------- scratch ----------------
__device__ float g_h[2][NH];
__device__ float g_q[NH], g_sk[NH];
__device__ __align__(16) __half g_kh[NH];                                // K fp16 (attention gather)
__device__ __align__(16) __half g_vh[NH];                                // V fp16 (attention gather)
__device__ __align__(256) __nv_bfloat16 g_hb[N_NODES * KTOT];            // A split [M, hi|lo]
__device__ __align__(256) __nv_bfloat16 g_Wb[4 * N_LAYERS * 256 * KTOT]; // B split [N, hi|lo]
__device__ float g_M[46 * HID];
__device__ float g_bias[HID];
__device__ float g_skbias[N_LAYERS * HID];
__device__ int g_deg[N_NODES];
__device__ int g_offs[N_NODES + 1];
__device__ int g_bsum[NBLK];
__device__ int g_cursor[N_NODES];
__device__ int g_ssrc[N_EDGES];
__device__ int g_seid[N_EDGES];

__device__ __forceinline__ void split_store(float v, __nv_bfloat16* hi_p, __nv_bfloat16* lo_p) {
    __nv_bfloat16 h = __float2bfloat16(v);
    *hi_p = h;
    *lo_p = __float2bfloat16(v - __bfloat162float(h));
}
__device__ __forceinline__ float dot4(float4 a, float4 b) {
    return a.x * b.x + a.y * b.y + a.z * b.z + a.w * b.w;
}
__device__ __forceinline__ void split4(float4 v, uint2* hi, uint2* lo) {
    __nv_bfloat16 hx = __float2bfloat16(v.x), hy = __float2bfloat16(v.y);
    __nv_bfloat16 hz = __float2bfloat16(v.z), hw = __float2bfloat16(v.w);
    __nv_bfloat162 h01 = __nv_bfloat162(hx, hy), h23 = __nv_bfloat162(hz, hw);
    hi->x = *reinterpret_cast<uint32_t*>(&h01);
    hi->y = *reinterpret_cast<uint32_t*>(&h23);
    __nv_bfloat162 l01 = __nv_bfloat162(__float2bfloat16(v.x - __bfloat162float(hx)),
                                        __float2bfloat16(v.y - __bfloat162float(hy)));
    __nv_bfloat162 l23 = __nv_bfloat162(__float2bfloat16(v.z - __bfloat162float(hz)),
                                        __float2bfloat16(v.w - __bfloat162float(hw)));
    lo->x = *reinterpret_cast<uint32_t*>(&l01);
    lo->y = *reinterpret_cast<uint32_t*>(&l23);
}
__device__ __forceinline__ void cp16(void* dst_smem, const void* src) {
    uint32_t d = (uint32_t)__cvta_generic_to_shared(dst_smem);
    asm volatile("cp.async.cg.shared.global [%0], [%1], 16;" :: "r"(d), "l"(src));
}
#define CP_COMMIT() asm volatile("cp.async.commit_group;" ::: "memory")
#define CP_WAIT2() asm volatile("cp.async.wait_group 2;" ::: "memory")
#define CP_WAIT1() asm volatile("cp.async.wait_group 1;" ::: "memory")
#define CP_WAIT0() asm volatile("cp.async.wait_group 0;" ::: "memory")

// ---------------- weight conversion: W[K,N] fp32 -> Wb[N, 512] bf16 (hi|lo) ----------------
__global__ void wconv_kernel(const float* __restrict__ Wq, const float* __restrict__ Wk,
                             const float* __restrict__ Wv, const float* __restrict__ Wsk) {
    __shared__ float s[32][33];
    int z = blockIdx.z;
    int w = z / N_LAYERS, l = z % N_LAYERS;
    const float* src = (w == 0) ? Wq : (w == 1) ? Wk : (w == 2) ? Wv : Wsk;
    src += l * 65536;
    __nv_bfloat16* dst = g_Wb + (size_t)z * 256 * KTOT;
    int k0 = blockIdx.x * 32, n0 = blockIdx.y * 32;
    int tx = threadIdx.x & 31, ty = threadIdx.x >> 5;
#pragma unroll
    for (int it = 0; it < 4; it++) {
        int r = ty + it * 8;
        s[r][tx] = src[(k0 + r) * 256 + n0 + tx];
    }
    __syncthreads();
#pragma unroll
    for (int it = 0; it < 4; it++) {
        int r = ty + it * 8;
        float v = s[tx][r];
        split_store(v, dst + (size_t)(n0 + r) * KTOT + k0 + tx,
                    dst + (size_t)(n0 + r) * KTOT + 256 + k0 + tx);
    }
}

// ---------------- fused encoder weights + skip-bias fold ----------------
__global__ void fuse_kernel(const float* __restrict__ W_emb, const float* __restrict__ W_t,
                            const float* __restrict__ W_s, const float* __restrict__ W_f,
                            const float* __restrict__ b_emb, const float* __restrict__ b_t,
                            const float* __restrict__ b_s, const float* __restrict__ b_f,
                            const float* __restrict__ bskip, const float* __restrict__ be) {
    int c = threadIdx.x;
    int r = blockIdx.x;
    if (r < 36) {
        float a = 0.f;
        for (int k = 0; k < 256; k++) a += W_emb[r * 256 + k] * W_f[k * 256 + c];
        g_M[r * 256 + c] = a;
    } else if (r < 40) {
        int rr = r - 36;
        float a = 0.f;
        for (int k = 0; k < 256; k++) a += W_t[rr * 256 + k] * W_f[(256 + k) * 256 + c];
        g_M[r * 256 + c] = a;
    } else if (r < 46) {
        int rr = r - 40;
        float a = 0.f;
        for (int k = 0; k < 256; k++) a += W_s[rr * 256 + k] * W_f[(512 + k) * 256 + c];
        g_M[r * 256 + c] = a;
    } else if (r == 46) {
        float a = b_f[c];
        for (int k = 0; k < 256; k++) {
            a += b_emb[k] * W_f[k * 256 + c];
            a += b_t[k] * W_f[(256 + k) * 256 + c];
            a += b_s[k] * W_f[(512 + k) * 256 + c];
        }
        g_bias[c] = a;
    } else {
        int l = r - 47;
        g_skbias[l * 256 + c] = bskip[l * 256 + c] + be[l * 256 + c];
    }
}

// ---------------- encoder ----------------
__global__ void encoder_kernel(const float* __restrict__ x, const float* __restrict__ t,
                               const float* __restrict__ s, const float* __restrict__ ln_g,
                               const float* __restrict__ ln_b) {
    __shared__ float sM[46 * 256];
    __shared__ float sb[256];
    __shared__ float sin_v[46];
    __shared__ float red[16];
    int tid = threadIdx.x;
    for (int i = tid; i < 46 * 256; i += 256) sM[i] = g_M[i];
    sb[tid] = g_bias[tid];
    float lg = ln_g[tid], lb = ln_b[tid];
    __syncthreads();
    for (int node = blockIdx.x; node < N_NODES; node += gridDim.x) {
        if (tid < 36) sin_v[tid] = x[node * 36 + tid];
        else if (tid < 40) sin_v[tid] = t[node * 4 + (tid - 36)];
        else if (tid < 46) sin_v[tid] = s[node * 6 + (tid - 40)];
        __syncthreads();
        float acc = sb[tid];
#pragma unroll
        for (int r = 0; r < 46; r++) acc += sin_v[r] * sM[r * 256 + tid];
        float ssum = acc, ssq = acc * acc;
#pragma unroll
        for (int o = 16; o; o >>= 1) {
            ssum += __shfl_xor_sync(0xffffffffu, ssum, o);
            ssq += __shfl_xor_sync(0xffffffffu, ssq, o);
        }
        if ((tid & 31) == 0) { red[tid >> 5] = ssum; red[8 + (tid >> 5)] = ssq; }
        __syncthreads();
        if (tid < 32) {
            float a = (tid < 8) ? red[tid] : 0.f;
            float b = (tid < 8) ? red[8 + tid] : 0.f;
#pragma unroll
            for (int o = 4; o; o >>= 1) {
                a += __shfl_xor_sync(0xffffffffu, a, o);
                b += __shfl_xor_sync(0xffffffffu, b, o);
            }
            if (tid == 0) { red[0] = a; red[1] = b; }
        }
        __syncthreads();
        float mu = red[0] * (1.f / 256.f);
        float var = red[1] * (1.f / 256.f) - mu * mu;
        float val = fmaxf((acc - mu) * rsqrtf(var + 1e-5f) * lg + lb, 0.f);
        g_h[0][node * 256 + tid] = val;
        split_store(val, g_hb + (size_t)node * KTOT + tid, g_hb + (size_t)node * KTOT + 256 + tid);
        __syncthreads();
    }
}

// ---------------- CSR build (3-phase scan) ----------------
__global__ void zero_deg_kernel() {
    int i = blockIdx.x * blockDim.x + threadIdx.x;
    if (i < N_NODES) g_deg[i] = 0;
}
__global__ void hist_kernel(const int* __restrict__ ei) {
    int e = blockIdx.x * blockDim.x + threadIdx.x;
    if (e < N_EDGES) atomicAdd(&g_deg[ei[N_EDGES + e]], 1);
}
__global__ void scanA_kernel() {
    __shared__ int wsum[8];
    int b = blockIdx.x, tid = threadIdx.x;
    int i = b * 256 + tid;
    int lane = tid & 31, wid = tid >> 5;
    int v = (i < N_NODES) ? g_deg[i] : 0;
    int x = v;
#pragma unroll
    for (int o = 1; o < 32; o <<= 1) {
        int y = __shfl_up_sync(0xffffffffu, x, o);
        if (lane >= o) x += y;
    }
    if (lane == 31) wsum[wid] = x;
    __syncthreads();
    if (wid == 0) {
        int s = (lane < 8) ? wsum[lane] : 0;
#pragma unroll
        for (int o = 1; o < 8; o <<= 1) {
            int y = __shfl_up_sync(0xffffffffu, s, o);
            if (lane >= o) s += y;
        }
        if (lane < 8) wsum[lane] = s;
    }
    __syncthreads();
    int base = (wid > 0) ? wsum[wid - 1] : 0;
    int incl = base + x;
    if (i < N_NODES) g_offs[i] = incl - v;
    if (tid == 255) g_bsum[b] = incl;
}
__global__ void scanB_kernel() {
    int total = 0;
    for (int b = 0; b < NBLK; b++) {
        int t = g_bsum[b];
        g_bsum[b] = total;
        total += t;
    }
    g_offs[N_NODES] = total;
}
__global__ void scanC_kernel() {
    int i = blockIdx.x * 256 + threadIdx.x;
    if (i < N_NODES) {
        int o = g_offs[i] + g_bsum[blockIdx.x];
        g_offs[i] = o;
        g_cursor[i] = o;
    }
}
__global__ void scatter_kernel(const int* __restrict__ ei) {
    int e = blockIdx.x * blockDim.x + threadIdx.x;
    if (e < N_EDGES) {
        int d = ei[N_EDGES + e];
        int pos = atomicAdd(&g_cursor[d], 1);
        g_ssrc[pos] = ei[e];
        g_seid[pos] = e;
    }
}

// ---------------- bf16 wmma GEMM, 128x128 tile, 4-stage cp.async pipeline ----------------
// w==0 -> g_q fp32; w==3 -> g_sk fp32; w==1 -> g_kh fp16 only; w==2 -> g_vh fp16 only.
__global__ void __launch_bounds__(256)
gemm_wb(int layer, const float* __restrict__ bq_, const float* __restrict__ bk_,
        const float* __restrict__ bv_) {
    extern __shared__ __align__(16) __nv_bfloat16 dyn[];  // NSTAGE * (A|B) stages
    __shared__ float sbias[128];

    int tid = threadIdx.x;
    int wid = tid >> 5, lane = tid & 31;
    int wr = wid >> 1, wc = wid & 1;
    int w = blockIdx.z;
    int row0 = blockIdx.x * 128;
    int colblk = blockIdx.y * 128;
    int col0 = colblk + wc * 64;

    const __nv_bfloat16* Bsrc = g_Wb + ((size_t)w * N_LAYERS + layer) * 256 * KTOT;
    float* C = nullptr;
    __half* Ch = nullptr;
    const float* bias;
    if (w == 0) { C = g_q; bias = bq_ + layer * 256; }
    else if (w == 1) { Ch = g_kh; bias = bk_ + layer * 256; }
    else if (w == 2) { Ch = g_vh; bias = bv_ + layer * 256; }
    else { C = g_sk; bias = g_skbias + layer * 256; }

    if (tid < 128) sbias[tid] = bias[colblk + tid];

    int l0 = tid, l1 = tid + 256;
    int ar0 = l0 >> 2, ak0 = (l0 & 3) * 8;
    int ar1 = l1 >> 2, ak1 = (l1 & 3) * 8;
    int gr0 = row0 + ar0; if (gr0 >= N_NODES) gr0 = N_NODES - 1;
    int gr1 = row0 + ar1; if (gr1 >= N_NODES) gr1 = N_NODES - 1;

    wmma::fragment<wmma::accumulator, 16, 16, 16, float> acc[2][4];
#pragma unroll
    for (int m = 0; m < 2; m++)
#pragma unroll
        for (int n = 0; n < 4; n++) wmma::fill_fragment(acc[m][n], 0.f);

    auto issue = [&](int c) {
        int seg = c >> 3, cc = c & 7;
        int aoff = (seg == 1) ? 256 : 0;
        int boff = (seg == 2) ? 256 : 0;
        __nv_bfloat16* As = dyn + (c & 3) * STAGE_ELEMS;
        __nv_bfloat16* Bs = As + 128 * GLDA;
        cp16(As + ar0 * GLDA + ak0, g_hb + (size_t)gr0 * KTOT + aoff + cc * GKCH + ak0);
        cp16(As + ar1 * GLDA + ak1, g_hb + (size_t)gr1 * KTOT + aoff + cc * GKCH + ak1);
        cp16(Bs + ar0 * GLDA + ak0, Bsrc + (size_t)(colblk + ar0) * KTOT + boff + cc * GKCH + ak0);
        cp16(Bs + ar1 * GLDA + ak1, Bsrc + (size_t)(colblk + ar1) * KTOT + boff + cc * GKCH + ak1);
        CP_COMMIT();
    };

    issue(0); issue(1); issue(2);
    for (int c = 0; c < GNCH; c++) {
        int rem = GNCH - 1 - c;
        if (rem >= 2) CP_WAIT2();
        else if (rem == 1) CP_WAIT1();
        else CP_WAIT0();
        __syncthreads();
        __nv_bfloat16* As = dyn + (c & 3) * STAGE_ELEMS;
        __nv_bfloat16* Bs = As + 128 * GLDA;
#pragma unroll
        for (int ks = 0; ks < 2; ks++) {
            wmma::fragment<wmma::matrix_a, 16, 16, 16, __nv_bfloat16, wmma::row_major> af[2];
            wmma::fragment<wmma::matrix_b, 16, 16, 16, __nv_bfloat16, wmma::col_major> bf[4];
#pragma unroll
            for (int m = 0; m < 2; m++)
                wmma::load_matrix_sync(af[m], As + (wr * 32 + m * 16) * GLDA + ks * 16, GLDA);
#pragma unroll
            for (int n = 0; n < 4; n++)
                wmma::load_matrix_sync(bf[n], Bs + (wc * 64 + n * 16) * GLDA + ks * 16, GLDA);
#pragma unroll
            for (int m = 0; m < 2; m++)
#pragma unroll
                for (int n = 0; n < 4; n++) wmma::mma_sync(acc[m][n], af[m], bf[n], acc[m][n]);
        }
        if (c + 3 < GNCH) issue(c + 3);
    }
    __syncthreads();

    float* stage = reinterpret_cast<float*>(dyn) + wid * 16 * LDS_STAGE;
#pragma unroll
    for (int m = 0; m < 2; m++) {
        __syncwarp();
#pragma unroll
        for (int n = 0; n < 4; n++)
            wmma::store_matrix_sync(stage + n * 16, acc[m][n], LDS_STAGE, wmma::mem_row_major);
        __syncwarp();
        int rbase = row0 + wr * 32 + m * 16;
#pragma unroll
        for (int i = lane; i < 16 * 64; i += 32) {
            int r = i >> 6, cc2 = i & 63;
            int gr = rbase + r;
            if (gr < N_NODES) {
                float val = stage[r * LDS_STAGE + cc2] + sbias[wc * 64 + cc2];
                size_t idx = (size_t)gr * 256 + col0 + cc2;
                if (C) C[idx] = val;
                else Ch[idx] = __float2half(val);
            }
        }
        __syncwarp();
    }
}

// ---------------- attention: lane-owned edge features, fp16 K+V gather, occ 5 ----------------
__global__ void __launch_bounds__(256, 5)
attn_kernel(const float* __restrict__ We_l, const float* __restrict__ edge_attr, int pin) {
    __shared__ float sWe[8 * 256];
    for (int i = threadIdx.x; i < 2048; i += blockDim.x) sWe[i] = We_l[i];
    __syncthreads();
    const float4* sWe4 = reinterpret_cast<const float4*>(sWe);
    int w = (blockIdx.x * blockDim.x + threadIdx.x) >> 5;
    int lane = threadIdx.x & 31;
    if (w >= N_NODES) return;
    float* hout = g_h[pin ^ 1];

    float4 q0 = *reinterpret_cast<const float4*>(g_q + (size_t)w * 256 + lane * 4);
    float4 q1 = *reinterpret_cast<const float4*>(g_q + (size_t)w * 256 + 128 + lane * 4);

    float qwe_own = 0.f;
#pragma unroll
    for (int d = 0; d < 8; d++) {
        float p = dot4(q0, sWe4[d * 64 + lane]) + dot4(q1, sWe4[d * 64 + 32 + lane]);
#pragma unroll
        for (int o = 16; o; o >>= 1) p += __shfl_xor_sync(0xffffffffu, p, o);
        if (lane == d) qwe_own = p;
    }

    float m = -INFINITY, den = 0.f;
    float4 acc0 = make_float4(0, 0, 0, 0), acc1 = make_float4(0, 0, 0, 0);
    float pea_own = 0.f;
    int beg = g_offs[w], end = g_offs[w + 1];
    for (int t = beg; t < end; t++) {
        int src = g_ssrc[t];
        int eid = g_seid[t];
        const uint2* khr = reinterpret_cast<const uint2*>(g_kh + (size_t)src * 256);
        const uint2* vhr = reinterpret_cast<const uint2*>(g_vh + (size_t)src * 256);
        uint2 ka = khr[lane];
        uint2 kb = khr[32 + lane];
        uint2 va = vhr[lane];
        uint2 vb = vhr[32 + lane];
        float e_own = (lane < 8) ? __ldg(edge_attr + (size_t)eid * 8 + lane) : 0.f;

        float2 ka01 = __half22float2(*reinterpret_cast<__half2*>(&ka.x));
        float2 ka23 = __half22float2(*reinterpret_cast<__half2*>(&ka.y));
        float2 kb01 = __half22float2(*reinterpret_cast<__half2*>(&kb.x));
        float2 kb23 = __half22float2(*reinterpret_cast<__half2*>(&kb.y));
        float2 va01 = __half22float2(*reinterpret_cast<__half2*>(&va.x));
        float2 va23 = __half22float2(*reinterpret_cast<__half2*>(&va.y));
        float2 vb01 = __half22float2(*reinterpret_cast<__half2*>(&vb.x));
        float2 vb23 = __half22float2(*reinterpret_cast<__half2*>(&vb.y));

        float partial = q0.x * ka01.x + q0.y * ka01.y + q0.z * ka23.x + q0.w * ka23.y +
                        q1.x * kb01.x + q1.y * kb01.y + q1.z * kb23.x + q1.w * kb23.y +
                        qwe_own * e_own;
#pragma unroll
        for (int o = 16; o; o >>= 1) partial += __shfl_xor_sync(0xffffffffu, partial, o);
        float alpha = partial * 0.0625f;
        float mn = fmaxf(m, alpha);
        float corr = __expf(m - mn);
        float p = __expf(alpha - mn);
        m = mn;
        den = den * corr + p;
        acc0.x = acc0.x * corr + p * va01.x; acc0.y = acc0.y * corr + p * va01.y;
        acc0.z = acc0.z * corr + p * va23.x; acc0.w = acc0.w * corr + p * va23.y;
        acc1.x = acc1.x * corr + p * vb01.x; acc1.y = acc1.y * corr + p * vb01.y;
        acc1.z = acc1.z * corr + p * vb23.x; acc1.w = acc1.w * corr + p * vb23.y;
        pea_own = pea_own * corr + p * e_own;
    }
    float inv = 1.f / (den + 1e-16f);
    float pe[8];
#pragma unroll
    for (int d = 0; d < 8; d++) pe[d] = __shfl_sync(0xffffffffu, pea_own, d);
    float4 ex0 = make_float4(0, 0, 0, 0), ex1 = make_float4(0, 0, 0, 0);
#pragma unroll
    for (int d = 0; d < 8; d++) {
        float4 w0 = sWe4[d * 64 + lane], w1 = sWe4[d * 64 + 32 + lane];
        ex0.x += pe[d] * w0.x; ex0.y += pe[d] * w0.y; ex0.z += pe[d] * w0.z; ex0.w += pe[d] * w0.w;
        ex1.x += pe[d] * w1.x; ex1.y += pe[d] * w1.y; ex1.z += pe[d] * w1.z; ex1.w += pe[d] * w1.w;
    }
    float4 sk0 = *reinterpret_cast<const float4*>(g_sk + (size_t)w * 256 + lane * 4);
    float4 sk1 = *reinterpret_cast<const float4*>(g_sk + (size_t)w * 256 + 128 + lane * 4);
    float4 o0, o1;
    o0.x = fmaxf((acc0.x + ex0.x) * inv + sk0.x, 0.f);
    o0.y = fmaxf((acc0.y + ex0.y) * inv + sk0.y, 0.f);
    o0.z = fmaxf((acc0.z + ex0.z) * inv + sk0.z, 0.f);
    o0.w = fmaxf((acc0.w + ex0.w) * inv + sk0.w, 0.f);
    o1.x = fmaxf((acc1.x + ex1.x) * inv + sk1.x, 0.f);
    o1.y = fmaxf((acc1.y + ex1.y) * inv + sk1.y, 0.f);
    o1.z = fmaxf((acc1.z + ex1.z) * inv + sk1.z, 0.f);
    o1.w = fmaxf((acc1.w + ex1.w) * inv + sk1.w, 0.f);
    *reinterpret_cast<float4*>(hout + (size_t)w * 256 + lane * 4) = o0;
    *reinterpret_cast<float4*>(hout + (size_t)w * 256 + 128 + lane * 4) = o1;
    uint2 hi, lo;
    split4(o0, &hi, &lo);
    *reinterpret_cast<uint2*>(g_hb + (size_t)w * KTOT + lane * 4) = hi;
    *reinterpret_cast<uint2*>(g_hb + (size_t)w * KTOT + 256 + lane * 4) = lo;
    split4(o1, &hi, &lo);
    *reinterpret_cast<uint2*>(g_hb + (size_t)w * KTOT + 128 + lane * 4) = hi;
    *reinterpret_cast<uint2*>(g_hb + (size_t)w * KTOT + 256 + 128 + lane * 4) = lo;
}

// ---------------- decoder ----------------
__global__ void dec_kernel(const float* __restrict__ Wd, const float* __restrict__ bd,
                           float* __restrict__ out) {
    __shared__ float sW[18 * 256];
    __shared__ float sb[18];
    for (int i = threadIdx.x; i < 18 * 256; i += blockDim.x) {
        int j = i / 18, o = i % 18;
        sW[o * 256 + j] = Wd[i];
    }
    if (threadIdx.x < 18) sb[threadIdx.x] = bd[threadIdx.x];
    __syncthreads();
    int w = (blockIdx.x * blockDim.x + threadIdx.x) >> 5;
    int lane = threadIdx.x & 31;
    if (w >= N_NODES) return;
    const float* h = g_h[1];
    float hr[8];
#pragma unroll
    for (int i = 0; i < 8; i++) hr[i] = h[(size_t)w * 256 + lane + 32 * i];
    for (int o = 0; o < 18; o++) {
        float p = 0.f;
#pragma unroll
        for (int i = 0; i < 8; i++) p += hr[i] * sW[o * 256 + lane + 32 * i];
#pragma unroll
        for (int off = 16; off; off >>= 1) p += __shfl_xor_sync(0xffffffffu, p, off);
        if (lane == 0) out[w * 18 + o] = p + sb[o];
    }
}

// ---------------- launch ----------------
extern "C" void kernel_launch(void* const* d_in, const int* in_sizes, int n_in,
                              void* d_out, int out_size) {
    const float* x = (const float*)d_in[0];
    const int* ei = (const int*)d_in[1];
    const float* edge_attr = (const float*)d_in[2];
    const float* t = (const float*)d_in[3];
    const float* s = (const float*)d_in[4];
    const float* W_emb = (const float*)d_in[5];
    const float* b_emb = (const float*)d_in[6];
    const float* W_t = (const float*)d_in[7];
    const float* b_t = (const float*)d_in[8];
    const float* W_s = (const float*)d_in[9];
    const float* b_s = (const float*)d_in[10];
    const float* W_f = (const float*)d_in[11];
    const float* b_f = (const float*)d_in[12];
    const float* ln_g = (const float*)d_in[13];
    const float* ln_b = (const float*)d_in[14];
    const float* Wq = (const float*)d_in[15];
    const float* bq = (const float*)d_in[16];
    const float* Wk = (const float*)d_in[17];
    const float* bk = (const float*)d_in[18];
    const float* Wv = (const float*)d_in[19];
    const float* bv = (const float*)d_in[20];
    const float* We = (const float*)d_in[21];
    const float* be = (const float*)d_in[22];
    const float* Wskip = (const float*)d_in[23];
    const float* bskip = (const float*)d_in[24];
    const float* W_dec = (const float*)d_in[25];
    const float* b_dec = (const float*)d_in[26];
    float* out = (float*)d_out;
    (void)in_sizes; (void)n_in; (void)out_size;

    cudaFuncSetAttribute(gemm_wb, cudaFuncAttributeMaxDynamicSharedMemorySize, GEMM_DYN_BYTES);

    wconv_kernel<<<dim3(8, 8, 20), 256>>>(Wq, Wk, Wv, Wskip);                        // 0
    fuse_kernel<<<52, 256>>>(W_emb, W_t, W_s, W_f, b_emb, b_t, b_s, b_f, bskip, be); // 1
    encoder_kernel<<<296, 256>>>(x, t, s, ln_g, ln_b);                               // 2

    dim3 ggrid(157, 2, 4);
    gemm_wb<<<ggrid, 256, GEMM_DYN_BYTES>>>(0, bq, bk, bv);                          // 3 <- profiled

    zero_deg_kernel<<<NBLK, 256>>>();                   // 4
    hist_kernel<<<(N_EDGES + 255) / 256, 256>>>(ei);    // 5
    scanA_kernel<<<NBLK, 256>>>();                      // 6
    scanB_kernel<<<1, 1>>>();                           // 7
    scanC_kernel<<<NBLK, 256>>>();                      // 8
    scatter_kernel<<<(N_EDGES + 255) / 256, 256>>>(ei); // 9

    int attn_blocks = (N_NODES * 32 + 255) / 256;
    attn_kernel<<<attn_blocks, 256>>>(We + 0 * 2048, edge_attr, 0);                  // 10
    for (int L = 1; L < N_LAYERS; L++) {
        int pin = L & 1;
        gemm_wb<<<ggrid, 256, GEMM_DYN_BYTES>>>(L, bq, bk, bv);
        attn_kernel<<<attn_blocks, 256>>>(We + L * 2048, edge_attr, pin);
    }
    dec_kernel<<<attn_blocks, 256>>>(W_dec, b_dec, out);
}